// round 2
// baseline (speedup 1.0000x reference)
#include <cuda_runtime.h>

// Problem constants (shapes fixed by the dataset)
#define HEADS 4
#define DHEAD 32
#define CDIM  128            // channels
#define NTOT  147456         // 384*384

// ---------------- scratch (static device globals; no runtime allocation) ----------------
__device__ float g_qkv[3 * CDIM * NTOT];       // rows 0..127 q, 128..255 k, 256..383 v
__device__ float g_ctx[HEADS * DHEAD * DHEAD]; // unnormalized context [h][d][e]
__device__ float g_z[CDIM];                    // softmax denominators per (h,d)
__device__ float g_M[CDIM * CDIM];             // fused W_out * blockdiag(C^T/Z)

// ---------------- zero small accumulators ----------------
__global__ void zero_small_kernel() {
    int i = blockIdx.x * blockDim.x + threadIdx.x;
    if (i < HEADS * DHEAD * DHEAD) g_ctx[i] = 0.0f;
    if (i < CDIM) g_z[i] = 0.0f;
}

// ---------------- SGEMM core: C[M][N] = A[M][128] * B[128][N] + bias[M] ----------------
// BM=128, BN=64, K=128 (full depth in one stage), 128 threads, 8x8 register tile.
#define G_BM 128
#define G_BN 64
#define G_K  128
#define G_ASL 129   // padded lead dim for transposed A tile (conflict-free a-reads)
#define G_BSL 64
#define G_SMEM ((G_K * G_ASL + G_K * G_BSL) * 4)

__device__ __forceinline__ void sgemm_body(
    const float* __restrict__ A,    // [128 x 128] block of A (row-major, ld=128)
    const float* __restrict__ B,    // [128 x N], column window starts at bn*64
    const float* __restrict__ bias, // bias for the 128 A-rows of this block
    float* __restrict__ C,          // output rows (ld=N), same row window as A
    int N, int bn)
{
    extern __shared__ float sm[];
    float* As = sm;                 // As[k * G_ASL + m]
    float* Bs = sm + G_K * G_ASL;   // Bs[k * G_BSL + n]

    const int tid = threadIdx.x;
    const float* Bblk = B + (size_t)bn * G_BN;

    // Load A tile 128x128 (coalesced float4 along k), store transposed.
    #pragma unroll
    for (int it = 0; it < 32; it++) {
        int idx = tid + it * 128;          // 0..4095
        int m  = idx >> 5;                 // row
        int k4 = idx & 31;                 // float4 index along k
        float4 v = reinterpret_cast<const float4*>(A)[m * 32 + k4];
        int k = k4 * 4;
        As[(k + 0) * G_ASL + m] = v.x;
        As[(k + 1) * G_ASL + m] = v.y;
        As[(k + 2) * G_ASL + m] = v.z;
        As[(k + 3) * G_ASL + m] = v.w;
    }
    // Load B tile 128x64 (float4, coalesced)
    #pragma unroll
    for (int it = 0; it < 16; it++) {
        int idx = tid + it * 128;          // 0..2047
        int r  = idx >> 4;                 // k row
        int c4 = idx & 15;
        float4 v = reinterpret_cast<const float4*>(Bblk + (size_t)r * N)[c4];
        reinterpret_cast<float4*>(Bs + r * G_BSL)[c4] = v;
    }
    __syncthreads();

    const int tr8 = (tid >> 3) * 8;   // row offset within tile (16 thread-rows)
    const int tc8 = (tid & 7) * 8;    // col offset within tile (8 thread-cols)

    float acc[8][8];
    #pragma unroll
    for (int i = 0; i < 8; i++)
        #pragma unroll
        for (int j = 0; j < 8; j++) acc[i][j] = 0.0f;

    #pragma unroll 8
    for (int k = 0; k < G_K; k++) {
        float a[8];
        const float* as = As + k * G_ASL + tr8;
        #pragma unroll
        for (int i = 0; i < 8; i++) a[i] = as[i];
        float4 b0 = *reinterpret_cast<const float4*>(Bs + k * G_BSL + tc8);
        float4 b1 = *reinterpret_cast<const float4*>(Bs + k * G_BSL + tc8 + 4);
        float b[8] = {b0.x, b0.y, b0.z, b0.w, b1.x, b1.y, b1.z, b1.w};
        #pragma unroll
        for (int i = 0; i < 8; i++)
            #pragma unroll
            for (int j = 0; j < 8; j++)
                acc[i][j] += a[i] * b[j];
    }

    // epilogue: bias + store
    #pragma unroll
    for (int i = 0; i < 8; i++) {
        int row = tr8 + i;
        float bv = bias[row];
        float* crow = C + (size_t)row * N + bn * G_BN + tc8;
        float4 o0 = make_float4(acc[i][0] + bv, acc[i][1] + bv, acc[i][2] + bv, acc[i][3] + bv);
        float4 o1 = make_float4(acc[i][4] + bv, acc[i][5] + bv, acc[i][6] + bv, acc[i][7] + bv);
        reinterpret_cast<float4*>(crow)[0] = o0;
        reinterpret_cast<float4*>(crow)[1] = o1;
    }
}

// GEMM 1: qkv = W_qkv @ x + b_qkv ; writes into g_qkv (device global, no symbol query)
__global__ void __launch_bounds__(128, 2)
sgemm_qkv(const float* __restrict__ w_qkv, const float* __restrict__ x,
          const float* __restrict__ b_qkv, int N) {
    const int bm = blockIdx.y;   // 0..2 (q/k/v row blocks)
    sgemm_body(w_qkv + (size_t)bm * G_BM * G_K, x, b_qkv + bm * G_BM,
               g_qkv + (size_t)bm * G_BM * N, N, blockIdx.x);
}

// GEMM 2: y = M @ q + b_out ; reads g_M and g_qkv (q rows) directly
__global__ void __launch_bounds__(128, 2)
sgemm_out(const float* __restrict__ b_out, float* __restrict__ y, int N) {
    sgemm_body(g_M, g_qkv, b_out, y, N, blockIdx.x);
}

// ---------------- context accumulation ----------------
// ctx[h][d][e] += exp(k[h,d,n]) * v[h,e,n];  z[h,d] += exp(k[h,d,n])
// 256 threads = 8 warps: warp -> (head = w>>1, e-half = w&1). lane = d.
#define CTX_TN 64
#define CTX_KSL 68
#define CTX_VSL 64
#define CTX_SMEM ((128 * CTX_KSL + 128 * CTX_VSL) * 4)

__global__ void __launch_bounds__(256)
context_kernel(int N, int ntiles) {
    extern __shared__ float sm[];
    float* ks = sm;
    float* vs = sm + 128 * CTX_KSL;

    const int tid = threadIdx.x;
    const int lane = tid & 31;
    const int w = tid >> 5;
    const int h = w >> 1;
    const int e0 = (w & 1) * 16;
    const bool do_z = ((w & 1) == 0);

    const float* K = g_qkv + (size_t)CDIM * N;       // k rows 128..255
    const float* V = g_qkv + (size_t)2 * CDIM * N;   // v rows 256..383

    float acc[16];
    #pragma unroll
    for (int j = 0; j < 16; j++) acc[j] = 0.0f;
    float z = 0.0f;

    for (int t = blockIdx.x; t < ntiles; t += gridDim.x) {
        const int n0 = t * CTX_TN;
        __syncthreads();
        // stage k and v tiles: 128 rows x 64 cols each
        for (int i = tid; i < 128 * 16; i += 256) {
            int r  = i >> 4;
            int c4 = i & 15;
            float4 kv = reinterpret_cast<const float4*>(K + (size_t)r * N + n0)[c4];
            int c = c4 * 4;
            ks[r * CTX_KSL + c + 0] = kv.x;
            ks[r * CTX_KSL + c + 1] = kv.y;
            ks[r * CTX_KSL + c + 2] = kv.z;
            ks[r * CTX_KSL + c + 3] = kv.w;
            float4 vv = reinterpret_cast<const float4*>(V + (size_t)r * N + n0)[c4];
            reinterpret_cast<float4*>(vs + r * CTX_VSL)[c4] = vv;
        }
        __syncthreads();

        const float* krow = ks + (h * 32 + lane) * CTX_KSL;
        #pragma unroll 4
        for (int n = 0; n < CTX_TN; n += 4) {
            float4 kv = *reinterpret_cast<const float4*>(krow + n);
            float ex = __expf(kv.x);
            float ey = __expf(kv.y);
            float ez = __expf(kv.z);
            float ew = __expf(kv.w);
            if (do_z) z += (ex + ey) + (ez + ew);
            #pragma unroll
            for (int j = 0; j < 16; j++) {
                const float4 vv = *reinterpret_cast<const float4*>(vs + (h * 32 + e0 + j) * CTX_VSL + n);
                acc[j] += ex * vv.x;
                acc[j] += ey * vv.y;
                acc[j] += ez * vv.z;
                acc[j] += ew * vv.w;
            }
        }
    }

    float* ctxp = g_ctx + h * (DHEAD * DHEAD) + lane * DHEAD + e0;
    #pragma unroll
    for (int j = 0; j < 16; j++) atomicAdd(&ctxp[j], acc[j]);
    if (do_z) atomicAdd(&g_z[h * 32 + lane], z);
}

// ---------------- compose M = W_out * blockdiag(C^T / Z) ----------------
// M[o][h*32+d] = (1/Z[h,d]) * sum_e W_out[o][h*32+e] * ctx[h][d][e]
__global__ void compose_M_kernel(const float* __restrict__ w_out) {
    const int tid = threadIdx.x;
    const int o  = blockIdx.x * 2 + (tid >> 7);
    const int c2 = tid & 127;
    const int h = c2 >> 5, d = c2 & 31;
    const float invz = 1.0f / g_z[c2];
    const float* wrow = w_out + o * CDIM + h * 32;
    const float* cr = g_ctx + h * (DHEAD * DHEAD) + d * DHEAD;
    float s = 0.0f;
    #pragma unroll
    for (int e = 0; e < 32; e++) s += wrow[e] * cr[e];
    g_M[o * CDIM + c2] = s * invz;
}

// ---------------- launch ----------------
extern "C" void kernel_launch(void* const* d_in, const int* in_sizes, int n_in,
                              void* d_out, int out_size) {
    const float* x     = (const float*)d_in[0];   // (1,128,384,384)
    const float* w_qkv = (const float*)d_in[1];   // (384,128,1,1)
    const float* b_qkv = (const float*)d_in[2];   // (384)
    const float* w_out = (const float*)d_in[3];   // (128,128,1,1)
    const float* b_out = (const float*)d_in[4];   // (128)
    float* y = (float*)d_out;                     // (128,384,384)

    const int N = in_sizes[0] / CDIM;             // 147456
    const int ntiles = N / CTX_TN;                // 2304

    cudaFuncSetAttribute(sgemm_qkv, cudaFuncAttributeMaxDynamicSharedMemorySize, G_SMEM);
    cudaFuncSetAttribute(sgemm_out, cudaFuncAttributeMaxDynamicSharedMemorySize, G_SMEM);
    cudaFuncSetAttribute(context_kernel, cudaFuncAttributeMaxDynamicSharedMemorySize, CTX_SMEM);

    // 1) zero small accumulators
    zero_small_kernel<<<17, 256>>>();

    // 2) qkv = W_qkv @ x + b_qkv   (384 x N)
    {
        dim3 grid(N / G_BN, 3);
        sgemm_qkv<<<grid, 128, G_SMEM>>>(w_qkv, x, b_qkv, N);
    }

    // 3) streaming exp/context accumulation over k,v
    context_kernel<<<296, 256, CTX_SMEM>>>(N, ntiles);

    // 4) fold attention-apply into output projection: M = W_out * blockdiag(C^T/Z)
    compose_M_kernel<<<64, 256>>>(w_out);

    // 5) y = M @ q + b_out   (128 x N)
    {
        dim3 grid(N / G_BN, 1);
        sgemm_out<<<grid, 128, G_SMEM>>>(b_out, y, N);
    }
}

// round 3
// speedup vs baseline: 1.2717x; 1.2717x over previous
#include <cuda_runtime.h>

// Problem constants (shapes fixed by the dataset)
#define HEADS 4
#define DHEAD 32
#define CDIM  128            // channels
#define NTOT  147456         // 384*384

// ---------------- scratch (static device globals; no runtime allocation) ----------------
__device__ float g_kv[2 * CDIM * NTOT];        // rows 0..127 k, 128..255 v
__device__ float g_ctx[HEADS * DHEAD * DHEAD]; // unnormalized context [h][d][e]
__device__ float g_z[CDIM];                    // softmax denominators per (h,d)
__device__ float g_M[CDIM * CDIM];             // W_out * blockdiag(C^T/Z)
__device__ float g_M2[CDIM * CDIM];            // M * W_q  (q-projection folded in)
__device__ float g_b2[CDIM];                   // M * b_q + b_out

// ---------------- packed f32x2 helpers ----------------
#define FMA2(d, a, b) asm("fma.rn.f32x2 %0, %1, %2, %0;" : "+l"(d) : "l"(a), "l"(b))
#define PACK_BCAST(p, x) asm("mov.b64 %0, {%1, %1};" : "=l"(p) : "f"(x))
#define PACK2(p, x, y)   asm("mov.b64 %0, {%1, %2};" : "=l"(p) : "f"(x), "f"(y))
#define UNPACK2(lo, hi, p) asm("mov.b64 {%0, %1}, %2;" : "=f"(lo), "=f"(hi) : "l"(p))

// ---------------- zero small accumulators ----------------
__global__ void zero_small_kernel() {
    int i = blockIdx.x * blockDim.x + threadIdx.x;
    if (i < HEADS * DHEAD * DHEAD) g_ctx[i] = 0.0f;
    if (i < CDIM) g_z[i] = 0.0f;
}

// ---------------- SGEMM core: C[128][N] = A[128][128] * B[128][N] + bias ----------------
// BM=128, BN=64, K=128 (full depth, one stage), 128 threads, 8x8 register tile,
// inner product done with packed fma.rn.f32x2 (2 MACs per issue slot).
#define G_BM 128
#define G_BN 64
#define G_K  128
#define G_ASL 129   // padded lead dim for transposed A tile (conflict-free)
#define G_BSL 64
#define G_SMEM ((G_K * G_ASL + G_K * G_BSL) * 4)

__device__ __forceinline__ void sgemm_body(
    const float* __restrict__ A,    // [128 x 128] block of A (row-major, ld=128)
    const float* __restrict__ B,    // [128 x N], column window starts at bn*64
    const float* __restrict__ bias, // bias for the 128 rows
    float* __restrict__ C,          // output rows (ld=N)
    int N, int bn)
{
    extern __shared__ float sm[];
    float* As = sm;                 // As[k * G_ASL + m]
    float* Bs = sm + G_K * G_ASL;   // Bs[k * G_BSL + n]

    const int tid = threadIdx.x;
    const float* Bblk = B + (size_t)bn * G_BN;

    // Load A tile 128x128 (coalesced float4 along k), store transposed.
    #pragma unroll
    for (int it = 0; it < 32; it++) {
        int idx = tid + it * 128;          // 0..4095
        int m  = idx >> 5;
        int k4 = idx & 31;
        float4 v = reinterpret_cast<const float4*>(A)[m * 32 + k4];
        int k = k4 * 4;
        As[(k + 0) * G_ASL + m] = v.x;
        As[(k + 1) * G_ASL + m] = v.y;
        As[(k + 2) * G_ASL + m] = v.z;
        As[(k + 3) * G_ASL + m] = v.w;
    }
    // Load B tile 128x64 (float4, coalesced)
    #pragma unroll
    for (int it = 0; it < 16; it++) {
        int idx = tid + it * 128;          // 0..2047
        int r  = idx >> 4;
        int c4 = idx & 15;
        float4 v = reinterpret_cast<const float4*>(Bblk + (size_t)r * N)[c4];
        reinterpret_cast<float4*>(Bs + r * G_BSL)[c4] = v;
    }
    __syncthreads();

    const int tr8 = (tid >> 3) * 8;   // row offset (16 thread-rows)
    const int tc8 = (tid & 7) * 8;    // col offset (8 thread-cols)

    // acc2[i][j]: packed pair (col 2j, col 2j+1) for row i
    unsigned long long acc2[8][4];
    #pragma unroll
    for (int i = 0; i < 8; i++)
        #pragma unroll
        for (int j = 0; j < 4; j++) acc2[i][j] = 0ULL;

    #pragma unroll 4
    for (int k = 0; k < G_K; k++) {
        const float* as = As + k * G_ASL + tr8;
        unsigned long long pa[8];
        #pragma unroll
        for (int i = 0; i < 8; i++) { float a = as[i]; PACK_BCAST(pa[i], a); }
        const ulonglong2 b01 = *reinterpret_cast<const ulonglong2*>(Bs + k * G_BSL + tc8);
        const ulonglong2 b23 = *reinterpret_cast<const ulonglong2*>(Bs + k * G_BSL + tc8 + 4);
        unsigned long long pb[4] = {b01.x, b01.y, b23.x, b23.y};
        #pragma unroll
        for (int i = 0; i < 8; i++) {
            FMA2(acc2[i][0], pa[i], pb[0]);
            FMA2(acc2[i][1], pa[i], pb[1]);
            FMA2(acc2[i][2], pa[i], pb[2]);
            FMA2(acc2[i][3], pa[i], pb[3]);
        }
    }

    // epilogue: unpack, bias, store
    #pragma unroll
    for (int i = 0; i < 8; i++) {
        int row = tr8 + i;
        float bv = bias[row];
        float c[8];
        #pragma unroll
        for (int j = 0; j < 4; j++) UNPACK2(c[2*j], c[2*j+1], acc2[i][j]);
        float* crow = C + (size_t)row * N + bn * G_BN + tc8;
        float4 o0 = make_float4(c[0] + bv, c[1] + bv, c[2] + bv, c[3] + bv);
        float4 o1 = make_float4(c[4] + bv, c[5] + bv, c[6] + bv, c[7] + bv);
        reinterpret_cast<float4*>(crow)[0] = o0;
        reinterpret_cast<float4*>(crow)[1] = o1;
    }
}

// GEMM 1: k,v = W_kv @ x + b_kv  (q rows are never computed)
__global__ void __launch_bounds__(128, 2)
sgemm_kv(const float* __restrict__ w_qkv, const float* __restrict__ x,
         const float* __restrict__ b_qkv, int N) {
    const int bm = blockIdx.y;   // 0 -> k (W rows 128..255), 1 -> v (rows 256..383)
    sgemm_body(w_qkv + (size_t)(1 + bm) * G_BM * G_K, x, b_qkv + (1 + bm) * G_BM,
               g_kv + (size_t)bm * G_BM * N, N, blockIdx.x);
}

// GEMM 2: y = M2 @ x + b2   (attention-apply + q-proj + out-proj all folded)
__global__ void __launch_bounds__(128, 2)
sgemm_out(const float* __restrict__ x, float* __restrict__ y, int N) {
    sgemm_body(g_M2, x, g_b2, y, N, blockIdx.x);
}

// ---------------- context accumulation ----------------
// ctx[h][d][e] += exp(k[h,d,n]) * v[h,e,n];  z[h,d] += exp(k[h,d,n])
// 256 threads = 8 warps: warp -> (head = w>>1, e-half = w&1). lane = d.
#define CTX_TN 64
#define CTX_KSL 68
#define CTX_VSL 64
#define CTX_SMEM ((128 * CTX_KSL + 128 * CTX_VSL) * 4)

__global__ void __launch_bounds__(256)
context_kernel(int N, int ntiles) {
    extern __shared__ float sm[];
    float* ks = sm;
    float* vs = sm + 128 * CTX_KSL;

    const int tid = threadIdx.x;
    const int lane = tid & 31;
    const int w = tid >> 5;
    const int h = w >> 1;
    const int e0 = (w & 1) * 16;
    const bool do_z = ((w & 1) == 0);

    const float* K = g_kv;                      // k rows 0..127
    const float* V = g_kv + (size_t)CDIM * N;   // v rows 128..255

    // packed accumulators: pair = (even-n partial, odd-n partial)
    unsigned long long acc2[16];
    #pragma unroll
    for (int j = 0; j < 16; j++) acc2[j] = 0ULL;
    float z = 0.0f;

    for (int t = blockIdx.x; t < ntiles; t += gridDim.x) {
        const int n0 = t * CTX_TN;
        __syncthreads();
        // stage k and v tiles: 128 rows x 64 cols each
        for (int i = tid; i < 128 * 16; i += 256) {
            int r  = i >> 4;
            int c4 = i & 15;
            float4 kv = reinterpret_cast<const float4*>(K + (size_t)r * N + n0)[c4];
            int c = c4 * 4;
            ks[r * CTX_KSL + c + 0] = kv.x;
            ks[r * CTX_KSL + c + 1] = kv.y;
            ks[r * CTX_KSL + c + 2] = kv.z;
            ks[r * CTX_KSL + c + 3] = kv.w;
            float4 vv = reinterpret_cast<const float4*>(V + (size_t)r * N + n0)[c4];
            reinterpret_cast<float4*>(vs + r * CTX_VSL)[c4] = vv;
        }
        __syncthreads();

        const float* krow = ks + (h * 32 + lane) * CTX_KSL;
        #pragma unroll 4
        for (int n = 0; n < CTX_TN; n += 4) {
            float4 kv = *reinterpret_cast<const float4*>(krow + n);
            float ex = __expf(kv.x);
            float ey = __expf(kv.y);
            float ez = __expf(kv.z);
            float ew = __expf(kv.w);
            if (do_z) z += (ex + ey) + (ez + ew);
            unsigned long long p01, p23;
            PACK2(p01, ex, ey);
            PACK2(p23, ez, ew);
            #pragma unroll
            for (int j = 0; j < 16; j++) {
                const ulonglong2 vv = *reinterpret_cast<const ulonglong2*>(
                    vs + (h * 32 + e0 + j) * CTX_VSL + n);
                FMA2(acc2[j], p01, vv.x);
                FMA2(acc2[j], p23, vv.y);
            }
        }
    }

    float* ctxp = g_ctx + h * (DHEAD * DHEAD) + lane * DHEAD + e0;
    #pragma unroll
    for (int j = 0; j < 16; j++) {
        float lo, hi;
        UNPACK2(lo, hi, acc2[j]);
        atomicAdd(&ctxp[j], lo + hi);
    }
    if (do_z) atomicAdd(&g_z[h * 32 + lane], z);
}

// ---------------- compose M = W_out * blockdiag(C^T / Z) ----------------
// M[o][h*32+d] = (1/Z[h,d]) * sum_e W_out[o][h*32+e] * ctx[h][d][e]
__global__ void compose_M_kernel(const float* __restrict__ w_out) {
    const int tid = threadIdx.x;
    const int o  = blockIdx.x * 2 + (tid >> 7);
    const int c2 = tid & 127;
    const int h = c2 >> 5, d = c2 & 31;
    const float invz = 1.0f / g_z[c2];
    const float* wrow = w_out + o * CDIM + h * 32;
    const float* cr = g_ctx + h * (DHEAD * DHEAD) + d * DHEAD;
    float s = 0.0f;
    #pragma unroll
    for (int e = 0; e < 32; e++) s += wrow[e] * cr[e];
    g_M[o * CDIM + c2] = s * invz;
}

// ---------------- compose M2 = M * W_q ;  b2 = M * b_q + b_out ----------------
__global__ void compose_M2_kernel(const float* __restrict__ w_qkv,
                                  const float* __restrict__ b_qkv,
                                  const float* __restrict__ b_out) {
    const int tid = threadIdx.x;
    const int o = blockIdx.x * 2 + (tid >> 7);
    const int c = tid & 127;
    const float* mrow = g_M + o * CDIM;
    float s = 0.0f;
    #pragma unroll 8
    for (int j = 0; j < CDIM; j++) s += mrow[j] * w_qkv[j * CDIM + c];
    g_M2[o * CDIM + c] = s;
    if (c == 0) {
        float b = b_out[o];
        #pragma unroll 8
        for (int j = 0; j < CDIM; j++) b += mrow[j] * b_qkv[j];
        g_b2[o] = b;
    }
}

// ---------------- launch ----------------
extern "C" void kernel_launch(void* const* d_in, const int* in_sizes, int n_in,
                              void* d_out, int out_size) {
    const float* x     = (const float*)d_in[0];   // (1,128,384,384)
    const float* w_qkv = (const float*)d_in[1];   // (384,128,1,1)
    const float* b_qkv = (const float*)d_in[2];   // (384)
    const float* w_out = (const float*)d_in[3];   // (128,128,1,1)
    const float* b_out = (const float*)d_in[4];   // (128)
    float* y = (float*)d_out;                     // (128,384,384)

    const int N = in_sizes[0] / CDIM;             // 147456
    const int ntiles = N / CTX_TN;                // 2304

    cudaFuncSetAttribute(sgemm_kv, cudaFuncAttributeMaxDynamicSharedMemorySize, G_SMEM);
    cudaFuncSetAttribute(sgemm_out, cudaFuncAttributeMaxDynamicSharedMemorySize, G_SMEM);
    cudaFuncSetAttribute(context_kernel, cudaFuncAttributeMaxDynamicSharedMemorySize, CTX_SMEM);

    // 1) zero small accumulators
    zero_small_kernel<<<17, 256>>>();

    // 2) k,v = W_kv @ x + b_kv   (256 x N; q never materialized)
    {
        dim3 grid(N / G_BN, 2);
        sgemm_kv<<<grid, 128, G_SMEM>>>(w_qkv, x, b_qkv, N);
    }

    // 3) streaming exp/context accumulation over k,v
    context_kernel<<<296, 256, CTX_SMEM>>>(N, ntiles);

    // 4) M = W_out * blockdiag(C^T/Z), then fold q-projection: M2 = M*W_q, b2 = M*b_q + b_out
    compose_M_kernel<<<64, 256>>>(w_out);
    compose_M2_kernel<<<64, 256>>>(w_qkv, b_qkv, b_out);

    // 5) y = M2 @ x + b2   (128 x N)
    {
        dim3 grid(N / G_BN, 1);
        sgemm_out<<<grid, 128, G_SMEM>>>(x, y, N);
    }
}

// round 5
// speedup vs baseline: 1.8978x; 1.4924x over previous
#include <cuda_runtime.h>
#include <cuda_bf16.h>
#include <cstdint>

// Problem constants (fixed by the dataset)
#define HEADS 4
#define DHEAD 32
#define CDIM  128
#define NTOT  147456          // 384*384
#define NT    64              // n-tile width for tensor GEMMs
#define NTILES (NTOT / NT)    // 2304
#define TILE_ELEMS (NT * CDIM) // 8192 bf16 per tile image
#define GRID_G 288            // GEMM grid.x; each block loops NTILES/GRID_G tiles

// ---------------- scratch (static device globals) ----------------
__device__ __align__(16) float g_kv[2 * CDIM * NTOT];   // k rows 0..127, v rows 128..255
__device__ float g_ctx[HEADS * DHEAD * DHEAD];
__device__ float g_z[CDIM];
__device__ float g_M[CDIM * CDIM];
__device__ float g_M2[CDIM * CDIM];
__device__ float g_b2[CDIM];
__device__ __align__(16) __nv_bfloat16 g_bh[(size_t)NTILES * TILE_ELEMS]; // x tiles, hi, dense [64][128]
__device__ __align__(16) __nv_bfloat16 g_bl[(size_t)NTILES * TILE_ELEMS]; // x tiles, lo
__device__ __align__(16) __nv_bfloat16 g_wh[2 * 16384];  // k,v weight hi images, dense [128][128]
__device__ __align__(16) __nv_bfloat16 g_wl[2 * 16384];  // k,v weight lo
__device__ __align__(16) __nv_bfloat16 g_m2h[16384];     // M2 hi
__device__ __align__(16) __nv_bfloat16 g_m2l[16384];     // M2 lo

// ---------------- portable tensor-core primitives (compute_103-safe) ----------------
__device__ __forceinline__ uint32_t smem_u32(const void* p) {
    uint32_t a;
    asm("{ .reg .u64 t; cvta.to.shared.u64 t, %1; cvt.u32.u64 %0, t; }" : "=r"(a) : "l"(p));
    return a;
}
#define LDM_X4(r0, r1, r2, r3, addr) \
    asm volatile("ldmatrix.sync.aligned.m8n8.x4.shared.b16 {%0,%1,%2,%3}, [%4];" \
                 : "=r"(r0), "=r"(r1), "=r"(r2), "=r"(r3) : "r"(addr))
#define MMA16816(d, a0, a1, a2, a3, b0, b1) \
    asm volatile("mma.sync.aligned.m16n8k16.row.col.f32.bf16.bf16.f32 " \
                 "{%0,%1,%2,%3}, {%4,%5,%6,%7}, {%8,%9}, {%0,%1,%2,%3};" \
                 : "+f"((d)[0]), "+f"((d)[1]), "+f"((d)[2]), "+f"((d)[3]) \
                 : "r"(a0), "r"(a1), "r"(a2), "r"(a3), "r"(b0), "r"(b1))

__device__ __forceinline__ uint32_t pack_bf2(float a, float b) {
    __nv_bfloat162 t = __floats2bfloat162_rn(a, b);
    return *reinterpret_cast<uint32_t*>(&t);
}

// ---------------- zero small accumulators ----------------
__global__ void zero_small_kernel() {
    int i = blockIdx.x * blockDim.x + threadIdx.x;
    if (i < HEADS * DHEAD * DHEAD) g_ctx[i] = 0.0f;
    if (i < CDIM) g_z[i] = 0.0f;
}

// ---------------- A-image prep: fp32 [128][128] -> dense bf16 hi/lo ----------------
__device__ __forceinline__ void build_a_images(const float* __restrict__ src,
                                               __nv_bfloat16* dh, __nv_bfloat16* dl) {
    const int tid = threadIdx.x;
    for (int c = tid; c < 2048; c += 256) {       // 2048 chunks of 8 elems
        int m = c >> 4, k0 = (c & 15) * 8;
        float4 x0 = *reinterpret_cast<const float4*>(src + m * 128 + k0);
        float4 x1 = *reinterpret_cast<const float4*>(src + m * 128 + k0 + 4);
        float v[8] = {x0.x, x0.y, x0.z, x0.w, x1.x, x1.y, x1.z, x1.w};
        uint32_t h[4], l[4];
        #pragma unroll
        for (int j = 0; j < 4; j++) {
            __nv_bfloat16 h0 = __float2bfloat16(v[2 * j]);
            __nv_bfloat16 h1 = __float2bfloat16(v[2 * j + 1]);
            h[j] = pack_bf2(__bfloat162float(h0), __bfloat162float(h1));
            l[j] = pack_bf2(v[2 * j] - __bfloat162float(h0),
                            v[2 * j + 1] - __bfloat162float(h1));
        }
        *reinterpret_cast<uint4*>(dh + m * 128 + k0) = make_uint4(h[0], h[1], h[2], h[3]);
        *reinterpret_cast<uint4*>(dl + m * 128 + k0) = make_uint4(l[0], l[1], l[2], l[3]);
    }
}
__global__ void prep_w_kernel(const float* __restrict__ w_qkv) {
    int b = blockIdx.x;  // 0 -> k weights (rows 128..255), 1 -> v (rows 256..383)
    build_a_images(w_qkv + (size_t)(1 + b) * 128 * 128, g_wh + b * 16384, g_wl + b * 16384);
}
__global__ void prep_m2_kernel() {
    build_a_images(g_M2, g_m2h, g_m2l);
}

// ---------------- x -> transposed, split bf16 tiles: dense [64 n][128 k] ----------------
__global__ void __launch_bounds__(256)
convert_x_kernel(const float* __restrict__ x, int N) {
    __shared__ float xt[128][65];
    const int t = blockIdx.x;
    const int n0 = t * NT;
    const int tid = threadIdx.x;
    for (int i = tid; i < 128 * 16; i += 256) {
        int c = i >> 4, q = (i & 15) * 4;
        float4 v = *reinterpret_cast<const float4*>(x + (size_t)c * N + n0 + q);
        xt[c][q + 0] = v.x; xt[c][q + 1] = v.y; xt[c][q + 2] = v.z; xt[c][q + 3] = v.w;
    }
    __syncthreads();
    __nv_bfloat16* dh = g_bh + (size_t)t * TILE_ELEMS;
    __nv_bfloat16* dl = g_bl + (size_t)t * TILE_ELEMS;
    for (int c = tid; c < 1024; c += 256) {
        int r = c >> 4, k0 = (c & 15) * 8;
        uint32_t h[4], l[4];
        #pragma unroll
        for (int j = 0; j < 4; j++) {
            float a = xt[k0 + 2 * j][r];
            float b = xt[k0 + 2 * j + 1][r];
            __nv_bfloat16 ha = __float2bfloat16(a);
            __nv_bfloat16 hb = __float2bfloat16(b);
            h[j] = pack_bf2(__bfloat162float(ha), __bfloat162float(hb));
            l[j] = pack_bf2(a - __bfloat162float(ha), b - __bfloat162float(hb));
        }
        *reinterpret_cast<uint4*>(dh + r * 128 + k0) = make_uint4(h[0], h[1], h[2], h[3]);
        *reinterpret_cast<uint4*>(dl + r * 128 + k0) = make_uint4(l[0], l[1], l[2], l[3]);
    }
}

// ---------------- HMMA GEMM body: out[128][tile 64] = A[128][128] @ Btile^T + bias ----------------
// 256 threads = 8 warps as 4(M)x2(N); per-warp 32x32; 3-term bf16 split.
#define LDA 136
#define LDB 136
#define SM_AH 0
#define SM_AL (128 * LDA * 2)
#define SM_BH (2 * 128 * LDA * 2)
#define SM_BL (2 * 128 * LDA * 2 + 64 * LDB * 2)
#define G_SMEM (2 * 128 * LDA * 2 + 2 * 64 * LDB * 2)   // 104448 bytes

__device__ __forceinline__ void gemm_body(
    const __nv_bfloat16* __restrict__ Ah, const __nv_bfloat16* __restrict__ Al,
    const float* __restrict__ bias, float* __restrict__ out, int N)
{
    extern __shared__ __align__(16) char sm[];
    const int tid = threadIdx.x, lane = tid & 31, w = tid >> 5;
    const int wm = w & 3, wn = w >> 2;

    // stage A hi/lo into padded smem (once per block)
    for (int i = tid; i < 128 * 16; i += 256) {
        int r = i >> 4, q = i & 15;
        *reinterpret_cast<uint4*>(sm + SM_AH + r * (LDA * 2) + q * 16) =
            reinterpret_cast<const uint4*>(Ah + r * 128)[q];
        *reinterpret_cast<uint4*>(sm + SM_AL + r * (LDA * 2) + q * 16) =
            reinterpret_cast<const uint4*>(Al + r * 128)[q];
    }

    const uint32_t uA = smem_u32(sm);
    // A fragment address: row m0+i*16+(lane&15), col ks*16+(lane>>4)*8
    const uint32_t a_row = wm * 32 + (lane & 15);
    const uint32_t a_col = (lane >> 4) * 8;
    // B fragment address (x4 covers 2 n-tiles): grp = lane>>3
    const int grp = lane >> 3;
    const uint32_t b_row0 = wn * 32 + (grp >> 1) * 8 + (lane & 7);  // + p*16
    const uint32_t b_col = (grp & 1) * 8;                            // + ks*16

    for (int t = blockIdx.x; t < NTILES; t += GRID_G) {
        __syncthreads();
        // stage B hi/lo tiles (16KB each) into padded smem
        {
            const uint4* bsrc = reinterpret_cast<const uint4*>(g_bh + (size_t)t * TILE_ELEMS);
            const uint4* lsrc = reinterpret_cast<const uint4*>(g_bl + (size_t)t * TILE_ELEMS);
            for (int i = tid; i < 64 * 16; i += 256) {
                int r = i >> 4, q = i & 15;
                *reinterpret_cast<uint4*>(sm + SM_BH + r * (LDB * 2) + q * 16) = bsrc[i];
                *reinterpret_cast<uint4*>(sm + SM_BL + r * (LDB * 2) + q * 16) = lsrc[i];
            }
        }
        __syncthreads();

        float acc[2][4][4];
        #pragma unroll
        for (int i = 0; i < 2; i++)
            #pragma unroll
            for (int j = 0; j < 4; j++)
                #pragma unroll
                for (int r = 0; r < 4; r++) acc[i][j][r] = 0.0f;

        #pragma unroll
        for (int ks = 0; ks < 8; ks++) {
            uint32_t ah[2][4], al[2][4], bh[2][4], bl[2][4];
            #pragma unroll
            for (int i = 0; i < 2; i++) {
                uint32_t off = ((a_row + i * 16) * LDA + ks * 16 + a_col) * 2;
                LDM_X4(ah[i][0], ah[i][1], ah[i][2], ah[i][3], uA + SM_AH + off);
                LDM_X4(al[i][0], al[i][1], al[i][2], al[i][3], uA + SM_AL + off);
            }
            #pragma unroll
            for (int p = 0; p < 2; p++) {
                uint32_t off = ((b_row0 + p * 16) * LDB + ks * 16 + b_col) * 2;
                LDM_X4(bh[p][0], bh[p][1], bh[p][2], bh[p][3], uA + SM_BH + off);
                LDM_X4(bl[p][0], bl[p][1], bl[p][2], bl[p][3], uA + SM_BL + off);
            }
            #pragma unroll
            for (int i = 0; i < 2; i++)
                #pragma unroll
                for (int j = 0; j < 4; j++) {
                    const int p = j >> 1, q = (j & 1) * 2;
                    // term 1: Ah*Bh
                    MMA16816(acc[i][j], ah[i][0], ah[i][1], ah[i][2], ah[i][3],
                             bh[p][q], bh[p][q + 1]);
                    // term 2: Ah*Bl
                    MMA16816(acc[i][j], ah[i][0], ah[i][1], ah[i][2], ah[i][3],
                             bl[p][q], bl[p][q + 1]);
                    // term 3: Al*Bh
                    MMA16816(acc[i][j], al[i][0], al[i][1], al[i][2], al[i][3],
                             bh[p][q], bh[p][q + 1]);
                }
        }

        // epilogue: bias + store fp32
        #pragma unroll
        for (int i = 0; i < 2; i++) {
            const int row = wm * 32 + i * 16 + (lane >> 2);
            const float b0 = bias[row], b1 = bias[row + 8];
            #pragma unroll
            for (int j = 0; j < 4; j++) {
                const int col = t * NT + wn * 32 + j * 8 + (lane & 3) * 2;
                float2 o0 = make_float2(acc[i][j][0] + b0, acc[i][j][1] + b0);
                float2 o1 = make_float2(acc[i][j][2] + b1, acc[i][j][3] + b1);
                *reinterpret_cast<float2*>(out + (size_t)row * N + col) = o0;
                *reinterpret_cast<float2*>(out + (size_t)(row + 8) * N + col) = o1;
            }
        }
    }
}

// GEMM 1: k,v = W_kv @ x + b_kv (blockIdx.y selects k or v)
__global__ void __launch_bounds__(256, 2)
gemm_kv_tc(const float* __restrict__ b_qkv, int N) {
    const int set = blockIdx.y;  // 0 -> k, 1 -> v
    gemm_body(g_wh + set * 16384, g_wl + set * 16384,
              b_qkv + 128 + set * 128, g_kv + (size_t)set * 128 * N, N);
}
// GEMM 2: y = M2 @ x + b2
__global__ void __launch_bounds__(256, 2)
gemm_out_tc(float* __restrict__ y, int N) {
    gemm_body(g_m2h, g_m2l, g_b2, y, N);
}

// ---------------- context accumulation (proven fp32 path) ----------------
#define FMA2(d, a, b) asm("fma.rn.f32x2 %0, %1, %2, %0;" : "+l"(d) : "l"(a), "l"(b))
#define PACK2(p, x, y)   asm("mov.b64 %0, {%1, %2};" : "=l"(p) : "f"(x), "f"(y))
#define UNPACK2(lo, hi, p) asm("mov.b64 {%0, %1}, %2;" : "=f"(lo), "=f"(hi) : "l"(p))

#define CTX_TN 64
#define CTX_KSL 68
#define CTX_VSL 64
#define CTX_SMEM ((128 * CTX_KSL + 128 * CTX_VSL) * 4)

__global__ void __launch_bounds__(256)
context_kernel(int N, int ntiles) {
    extern __shared__ float smf[];
    float* ks = smf;
    float* vs = smf + 128 * CTX_KSL;

    const int tid = threadIdx.x;
    const int lane = tid & 31;
    const int w = tid >> 5;
    const int h = w >> 1;
    const int e0 = (w & 1) * 16;
    const bool do_z = ((w & 1) == 0);

    const float* K = g_kv;
    const float* V = g_kv + (size_t)CDIM * N;

    unsigned long long acc2[16];
    #pragma unroll
    for (int j = 0; j < 16; j++) acc2[j] = 0ULL;
    float z = 0.0f;

    for (int t = blockIdx.x; t < ntiles; t += gridDim.x) {
        const int n0 = t * CTX_TN;
        __syncthreads();
        for (int i = tid; i < 128 * 16; i += 256) {
            int r = i >> 4, c4 = i & 15;
            float4 kv = reinterpret_cast<const float4*>(K + (size_t)r * N + n0)[c4];
            int c = c4 * 4;
            ks[r * CTX_KSL + c + 0] = kv.x;
            ks[r * CTX_KSL + c + 1] = kv.y;
            ks[r * CTX_KSL + c + 2] = kv.z;
            ks[r * CTX_KSL + c + 3] = kv.w;
            float4 vv = reinterpret_cast<const float4*>(V + (size_t)r * N + n0)[c4];
            reinterpret_cast<float4*>(vs + r * CTX_VSL)[c4] = vv;
        }
        __syncthreads();

        const float* krow = ks + (h * 32 + lane) * CTX_KSL;
        #pragma unroll 4
        for (int n = 0; n < CTX_TN; n += 4) {
            float4 kv = *reinterpret_cast<const float4*>(krow + n);
            float ex = __expf(kv.x), ey = __expf(kv.y);
            float ez = __expf(kv.z), ew = __expf(kv.w);
            if (do_z) z += (ex + ey) + (ez + ew);
            unsigned long long p01, p23;
            PACK2(p01, ex, ey);
            PACK2(p23, ez, ew);
            #pragma unroll
            for (int j = 0; j < 16; j++) {
                const ulonglong2 vv = *reinterpret_cast<const ulonglong2*>(
                    vs + (h * 32 + e0 + j) * CTX_VSL + n);
                FMA2(acc2[j], p01, vv.x);
                FMA2(acc2[j], p23, vv.y);
            }
        }
    }

    float* ctxp = g_ctx + h * (DHEAD * DHEAD) + lane * DHEAD + e0;
    #pragma unroll
    for (int j = 0; j < 16; j++) {
        float lo, hi;
        UNPACK2(lo, hi, acc2[j]);
        atomicAdd(&ctxp[j], lo + hi);
    }
    if (do_z) atomicAdd(&g_z[h * 32 + lane], z);
}

// ---------------- compose M and M2 (exact algebraic folds) ----------------
__global__ void compose_M_kernel(const float* __restrict__ w_out) {
    const int tid = threadIdx.x;
    const int o = blockIdx.x * 2 + (tid >> 7);
    const int c2 = tid & 127;
    const int h = c2 >> 5, d = c2 & 31;
    const float invz = 1.0f / g_z[c2];
    const float* wrow = w_out + o * CDIM + h * 32;
    const float* cr = g_ctx + h * (DHEAD * DHEAD) + d * DHEAD;
    float s = 0.0f;
    #pragma unroll
    for (int e = 0; e < 32; e++) s += wrow[e] * cr[e];
    g_M[o * CDIM + c2] = s * invz;
}
__global__ void compose_M2_kernel(const float* __restrict__ w_qkv,
                                  const float* __restrict__ b_qkv,
                                  const float* __restrict__ b_out) {
    const int tid = threadIdx.x;
    const int o = blockIdx.x * 2 + (tid >> 7);
    const int c = tid & 127;
    const float* mrow = g_M + o * CDIM;
    float s = 0.0f;
    #pragma unroll 8
    for (int j = 0; j < CDIM; j++) s += mrow[j] * w_qkv[j * CDIM + c];
    g_M2[o * CDIM + c] = s;
    if (c == 0) {
        float b = b_out[o];
        #pragma unroll 8
        for (int j = 0; j < CDIM; j++) b += mrow[j] * b_qkv[j];
        g_b2[o] = b;
    }
}

// ---------------- launch ----------------
extern "C" void kernel_launch(void* const* d_in, const int* in_sizes, int n_in,
                              void* d_out, int out_size) {
    const float* x     = (const float*)d_in[0];
    const float* w_qkv = (const float*)d_in[1];
    const float* b_qkv = (const float*)d_in[2];
    const float* w_out = (const float*)d_in[3];
    const float* b_out = (const float*)d_in[4];
    float* y = (float*)d_out;

    const int N = in_sizes[0] / CDIM;     // 147456
    const int ntiles = N / NT;            // 2304
    const int ctx_tiles = N / CTX_TN;

    cudaFuncSetAttribute(gemm_kv_tc,  cudaFuncAttributeMaxDynamicSharedMemorySize, G_SMEM);
    cudaFuncSetAttribute(gemm_out_tc, cudaFuncAttributeMaxDynamicSharedMemorySize, G_SMEM);
    cudaFuncSetAttribute(context_kernel, cudaFuncAttributeMaxDynamicSharedMemorySize, CTX_SMEM);

    zero_small_kernel<<<17, 256>>>();
    prep_w_kernel<<<2, 256>>>(w_qkv);
    convert_x_kernel<<<ntiles, 256>>>(x, N);

    {   // k,v = W_kv @ x + b_kv
        dim3 grid(GRID_G, 2);
        gemm_kv_tc<<<grid, 256, G_SMEM>>>(b_qkv, N);
    }

    context_kernel<<<296, 256, CTX_SMEM>>>(N, ctx_tiles);
    compose_M_kernel<<<64, 256>>>(w_out);
    compose_M2_kernel<<<64, 256>>>(w_qkv, b_qkv, b_out);
    prep_m2_kernel<<<1, 256>>>();

    // y = M2 @ x + b2
    gemm_out_tc<<<GRID_G, 256, G_SMEM>>>(y, N);
}

// round 7
// speedup vs baseline: 2.1459x; 1.1307x over previous
#include <cuda_runtime.h>
#include <cuda_bf16.h>
#include <cstdint>

// Problem constants (fixed by the dataset)
#define HEADS 4
#define DHEAD 32
#define CDIM  128
#define NTOT  147456          // 384*384
#define NT    64              // n-tile width
#define NTILES (NTOT / NT)    // 2304
#define GRID_G 288            // GEMM grid.x; tiles-per-block = NTILES/GRID_G = 8

// ---------------- scratch (static device globals) ----------------
__device__ __align__(16) float g_kv[2 * CDIM * NTOT];   // k rows 0..127, v rows 128..255
__device__ float g_ctx[HEADS * DHEAD * DHEAD];
__device__ float g_z[CDIM];
__device__ float g_M[CDIM * CDIM];
__device__ float g_M2[CDIM * CDIM];
__device__ float g_b2[CDIM];
__device__ __align__(16) __nv_bfloat16 g_wh[2 * 16384];  // k,v weight hi images [128][128]
__device__ __align__(16) __nv_bfloat16 g_wl[2 * 16384];  // k,v weight lo
__device__ __align__(16) __nv_bfloat16 g_m2h[16384];     // M2 hi
__device__ __align__(16) __nv_bfloat16 g_m2l[16384];     // M2 lo

// ---------------- portable primitives ----------------
__device__ __forceinline__ uint32_t smem_u32(const void* p) {
    uint32_t a;
    asm("{ .reg .u64 t; cvta.to.shared.u64 t, %1; cvt.u32.u64 %0, t; }" : "=r"(a) : "l"(p));
    return a;
}
#define LDM_X4(r0, r1, r2, r3, addr) \
    asm volatile("ldmatrix.sync.aligned.m8n8.x4.shared.b16 {%0,%1,%2,%3}, [%4];" \
                 : "=r"(r0), "=r"(r1), "=r"(r2), "=r"(r3) : "r"(addr))
#define LDM_X4_T(r0, r1, r2, r3, addr) \
    asm volatile("ldmatrix.sync.aligned.m8n8.x4.trans.shared.b16 {%0,%1,%2,%3}, [%4];" \
                 : "=r"(r0), "=r"(r1), "=r"(r2), "=r"(r3) : "r"(addr))
#define MMA16816(d, a0, a1, a2, a3, b0, b1) \
    asm volatile("mma.sync.aligned.m16n8k16.row.col.f32.bf16.bf16.f32 " \
                 "{%0,%1,%2,%3}, {%4,%5,%6,%7}, {%8,%9}, {%0,%1,%2,%3};" \
                 : "+f"((d)[0]), "+f"((d)[1]), "+f"((d)[2]), "+f"((d)[3]) \
                 : "r"(a0), "r"(a1), "r"(a2), "r"(a3), "r"(b0), "r"(b1))

__device__ __forceinline__ uint32_t pack_bf2(float a, float b) {
    __nv_bfloat162 t = __floats2bfloat162_rn(a, b);
    return *reinterpret_cast<uint32_t*>(&t);
}

// smem geometry
#define LDA  136                       // A image row stride (bf16 elems)
#define LDBN 72                        // B tile row stride (bf16 elems)
#define A_IMG (128 * LDA * 2)          // 34816 B per A image
#define B_IMG (128 * LDBN * 2)         // 18432 B per B buffer
// kv kernel: AH0 | AL0 | AH1 | AL1 | BH | BL
#define KV_BH (4 * A_IMG)
#define KV_BL (4 * A_IMG + B_IMG)
#define KV_SMEM (4 * A_IMG + 2 * B_IMG)   // 176128
// out kernel: AH | AL | BH | BL
#define OUT_BH (2 * A_IMG)
#define OUT_BL (2 * A_IMG + B_IMG)
#define OUT_SMEM (2 * A_IMG + 2 * B_IMG)  // 106496

// ---------------- zero small accumulators ----------------
__global__ void zero_small_kernel() {
    int i = blockIdx.x * blockDim.x + threadIdx.x;
    if (i < HEADS * DHEAD * DHEAD) g_ctx[i] = 0.0f;
    if (i < CDIM) g_z[i] = 0.0f;
}

// ---------------- A-image prep: fp32 [128][128] -> dense bf16 hi/lo ----------------
__device__ __forceinline__ void build_a_images(const float* __restrict__ src,
                                               __nv_bfloat16* dh, __nv_bfloat16* dl) {
    const int tid = threadIdx.x;
    for (int c = tid; c < 2048; c += 256) {
        int m = c >> 4, k0 = (c & 15) * 8;
        float4 x0 = *reinterpret_cast<const float4*>(src + m * 128 + k0);
        float4 x1 = *reinterpret_cast<const float4*>(src + m * 128 + k0 + 4);
        float v[8] = {x0.x, x0.y, x0.z, x0.w, x1.x, x1.y, x1.z, x1.w};
        uint32_t h[4], l[4];
        #pragma unroll
        for (int j = 0; j < 4; j++) {
            __nv_bfloat16 h0 = __float2bfloat16(v[2 * j]);
            __nv_bfloat16 h1 = __float2bfloat16(v[2 * j + 1]);
            h[j] = pack_bf2(__bfloat162float(h0), __bfloat162float(h1));
            l[j] = pack_bf2(v[2 * j] - __bfloat162float(h0),
                            v[2 * j + 1] - __bfloat162float(h1));
        }
        *reinterpret_cast<uint4*>(dh + m * 128 + k0) = make_uint4(h[0], h[1], h[2], h[3]);
        *reinterpret_cast<uint4*>(dl + m * 128 + k0) = make_uint4(l[0], l[1], l[2], l[3]);
    }
}
__global__ void prep_w_kernel(const float* __restrict__ w_qkv) {
    int b = blockIdx.x;  // 0 -> k weights (rows 128..255), 1 -> v (rows 256..383)
    build_a_images(w_qkv + (size_t)(1 + b) * 128 * 128, g_wh + b * 16384, g_wl + b * 16384);
}
__global__ void prep_m2_kernel() {
    build_a_images(g_M2, g_m2h, g_m2l);
}

// ---------------- HMMA tile computation over staged smem ----------------
__device__ __forceinline__ void mma_tile_body(
    uint32_t uSM, uint32_t offAh, uint32_t offAl, uint32_t offBh, uint32_t offBl,
    int lane, int wm, int wn, float acc[2][2][4])
{
    #pragma unroll
    for (int i = 0; i < 2; i++)
        #pragma unroll
        for (int j = 0; j < 2; j++)
            #pragma unroll
            for (int r = 0; r < 4; r++) acc[i][j][r] = 0.0f;

    const uint32_t a_row = wm * 32 + (lane & 15);
    const uint32_t a_col = (lane >> 4) * 8;
    const uint32_t b_krow = (lane & 7) + ((lane >> 3) & 1) * 8;   // within k16
    const uint32_t b_noff = ((lane >> 4) & 1) * 8;                // n-sub select

    #pragma unroll
    for (int ks = 0; ks < 8; ks++) {
        uint32_t ah[2][4], al[2][4], bh[4], bl[4];
        #pragma unroll
        for (int i = 0; i < 2; i++) {
            uint32_t off = ((a_row + i * 16) * LDA + ks * 16 + a_col) * 2;
            LDM_X4(ah[i][0], ah[i][1], ah[i][2], ah[i][3], uSM + offAh + off);
            LDM_X4(al[i][0], al[i][1], al[i][2], al[i][3], uSM + offAl + off);
        }
        {
            uint32_t boff = ((ks * 16 + b_krow) * LDBN + wn * 16 + b_noff) * 2;
            LDM_X4_T(bh[0], bh[1], bh[2], bh[3], uSM + offBh + boff);
            LDM_X4_T(bl[0], bl[1], bl[2], bl[3], uSM + offBl + boff);
        }
        #pragma unroll
        for (int i = 0; i < 2; i++)
            #pragma unroll
            for (int j = 0; j < 2; j++) {
                MMA16816(acc[i][j], ah[i][0], ah[i][1], ah[i][2], ah[i][3], bh[2*j], bh[2*j+1]);
                MMA16816(acc[i][j], ah[i][0], ah[i][1], ah[i][2], ah[i][3], bl[2*j], bl[2*j+1]);
                MMA16816(acc[i][j], al[i][0], al[i][1], al[i][2], al[i][3], bh[2*j], bh[2*j+1]);
            }
    }
}

__device__ __forceinline__ void store_acc(
    float* __restrict__ out, int N, int col0, int wm, int wn, int lane,
    const float acc[2][2][4], const float* __restrict__ bias)
{
    #pragma unroll
    for (int i = 0; i < 2; i++) {
        const int row = wm * 32 + i * 16 + (lane >> 2);
        const float b0 = bias[row], b1 = bias[row + 8];
        #pragma unroll
        for (int j = 0; j < 2; j++) {
            const int col = col0 + wn * 16 + j * 8 + (lane & 3) * 2;
            *reinterpret_cast<float2*>(out + (size_t)row * N + col) =
                make_float2(acc[i][j][0] + b0, acc[i][j][1] + b0);
            *reinterpret_cast<float2*>(out + (size_t)(row + 8) * N + col) =
                make_float2(acc[i][j][2] + b1, acc[i][j][3] + b1);
        }
    }
}

// load x tile [128c][64n] fp32 into 4 float4 regs (512 threads)
__device__ __forceinline__ void ldg_tile(float4 pf[4], const float* __restrict__ x,
                                         int N, int n0, int tid) {
    #pragma unroll
    for (int i = 0; i < 4; i++) {
        int idx = tid + i * 512, r = idx >> 4, q = idx & 15;
        pf[i] = *reinterpret_cast<const float4*>(x + (size_t)r * N + n0 + q * 4);
    }
}
// convert regs -> bf16 hi/lo smem tiles
__device__ __forceinline__ void sts_convert(const float4 pf[4], char* sm,
                                            uint32_t offBh, uint32_t offBl, int tid) {
    #pragma unroll
    for (int i = 0; i < 4; i++) {
        int idx = tid + i * 512, r = idx >> 4, q = idx & 15;
        float4 v = pf[i];
        __nv_bfloat16 hx = __float2bfloat16(v.x), hy = __float2bfloat16(v.y);
        __nv_bfloat16 hz = __float2bfloat16(v.z), hw = __float2bfloat16(v.w);
        uint2 hp = make_uint2(pack_bf2(__bfloat162float(hx), __bfloat162float(hy)),
                              pack_bf2(__bfloat162float(hz), __bfloat162float(hw)));
        uint2 lp = make_uint2(pack_bf2(v.x - __bfloat162float(hx), v.y - __bfloat162float(hy)),
                              pack_bf2(v.z - __bfloat162float(hz), v.w - __bfloat162float(hw)));
        *reinterpret_cast<uint2*>(sm + offBh + (r * LDBN + q * 4) * 2) = hp;
        *reinterpret_cast<uint2*>(sm + offBl + (r * LDBN + q * 4) * 2) = lp;
    }
}

// ---------------- GEMM 1: k,v = W_kv @ x + b_kv (both sets per block) ----------------
__global__ void __launch_bounds__(512, 1)
gemm_kv_tc(const float* __restrict__ x, const float* __restrict__ b_qkv, int N, int tpb) {
    extern __shared__ __align__(16) char sm[];
    const int tid = threadIdx.x, lane = tid & 31, w = tid >> 5;
    const int wm = w & 3, wn = w >> 2;
    const uint32_t uSM = smem_u32(sm);

    // stage 4 weight images (kh, kl, vh, vl)
    for (int i = tid; i < 8192; i += 512) {
        int img = i >> 11, rem = i & 2047, r = rem >> 4, q = rem & 15;
        int set = img >> 1;
        const __nv_bfloat16* srcb = (img & 1) ? g_wl : g_wh;
        uint4 v = reinterpret_cast<const uint4*>(srcb + set * 16384 + r * 128)[q];
        *reinterpret_cast<uint4*>(sm + img * A_IMG + (r * LDA + q * 8) * 2) = v;
    }

    int t = blockIdx.x;
    float4 pf[4];
    ldg_tile(pf, x, N, t * NT, tid);
    __syncthreads();

    for (int it = 0; it < tpb; it++, t += GRID_G) {
        sts_convert(pf, sm, KV_BH, KV_BL, tid);
        __syncthreads();
        if (it + 1 < tpb) ldg_tile(pf, x, N, (t + GRID_G) * NT, tid);

        float acc[2][2][4];
        mma_tile_body(uSM, 0, A_IMG, KV_BH, KV_BL, lane, wm, wn, acc);           // k
        store_acc(g_kv, N, t * NT, wm, wn, lane, acc, b_qkv + 128);
        mma_tile_body(uSM, 2 * A_IMG, 3 * A_IMG, KV_BH, KV_BL, lane, wm, wn, acc); // v
        store_acc(g_kv + (size_t)128 * N, N, t * NT, wm, wn, lane, acc, b_qkv + 256);
        __syncthreads();
    }
}

// ---------------- GEMM 2: y = M2 @ x + b2 ----------------
__global__ void __launch_bounds__(512, 2)
gemm_out_tc(const float* __restrict__ x, float* __restrict__ y, int N, int tpb) {
    extern __shared__ __align__(16) char sm[];
    const int tid = threadIdx.x, lane = tid & 31, w = tid >> 5;
    const int wm = w & 3, wn = w >> 2;
    const uint32_t uSM = smem_u32(sm);

    for (int i = tid; i < 4096; i += 512) {
        int img = i >> 11, rem = i & 2047, r = rem >> 4, q = rem & 15;
        const __nv_bfloat16* srcb = img ? g_m2l : g_m2h;
        uint4 v = reinterpret_cast<const uint4*>(srcb + r * 128)[q];
        *reinterpret_cast<uint4*>(sm + img * A_IMG + (r * LDA + q * 8) * 2) = v;
    }

    int t = blockIdx.x;
    float4 pf[4];
    ldg_tile(pf, x, N, t * NT, tid);
    __syncthreads();

    for (int it = 0; it < tpb; it++, t += GRID_G) {
        sts_convert(pf, sm, OUT_BH, OUT_BL, tid);
        __syncthreads();
        if (it + 1 < tpb) ldg_tile(pf, x, N, (t + GRID_G) * NT, tid);

        float acc[2][2][4];
        mma_tile_body(uSM, 0, A_IMG, OUT_BH, OUT_BL, lane, wm, wn, acc);
        store_acc(y, N, t * NT, wm, wn, lane, acc, g_b2);
        __syncthreads();
    }
}

// ---------------- context accumulation (proven fp32 path) ----------------
#define FMA2(d, a, b) asm("fma.rn.f32x2 %0, %1, %2, %0;" : "+l"(d) : "l"(a), "l"(b))
#define PACK2(p, x, y)   asm("mov.b64 %0, {%1, %2};" : "=l"(p) : "f"(x), "f"(y))
#define UNPACK2(lo, hi, p) asm("mov.b64 {%0, %1}, %2;" : "=f"(lo), "=f"(hi) : "l"(p))

#define CTX_TN 64
#define CTX_KSL 68
#define CTX_VSL 64
#define CTX_SMEM ((128 * CTX_KSL + 128 * CTX_VSL) * 4)

__global__ void __launch_bounds__(256)
context_kernel(int N, int ntiles) {
    extern __shared__ float smf[];
    float* ks = smf;
    float* vs = smf + 128 * CTX_KSL;

    const int tid = threadIdx.x;
    const int lane = tid & 31;
    const int w = tid >> 5;
    const int h = w >> 1;
    const int e0 = (w & 1) * 16;
    const bool do_z = ((w & 1) == 0);

    const float* K = g_kv;
    const float* V = g_kv + (size_t)CDIM * N;

    unsigned long long acc2[16];
    #pragma unroll
    for (int j = 0; j < 16; j++) acc2[j] = 0ULL;
    float z = 0.0f;

    for (int t = blockIdx.x; t < ntiles; t += gridDim.x) {
        const int n0 = t * CTX_TN;
        __syncthreads();
        for (int i = tid; i < 128 * 16; i += 256) {
            int r = i >> 4, c4 = i & 15;
            float4 kv = reinterpret_cast<const float4*>(K + (size_t)r * N + n0)[c4];
            int c = c4 * 4;
            ks[r * CTX_KSL + c + 0] = kv.x;
            ks[r * CTX_KSL + c + 1] = kv.y;
            ks[r * CTX_KSL + c + 2] = kv.z;
            ks[r * CTX_KSL + c + 3] = kv.w;
            float4 vv = reinterpret_cast<const float4*>(V + (size_t)r * N + n0)[c4];
            reinterpret_cast<float4*>(vs + r * CTX_VSL)[c4] = vv;
        }
        __syncthreads();

        const float* krow = ks + (h * 32 + lane) * CTX_KSL;
        #pragma unroll 4
        for (int n = 0; n < CTX_TN; n += 4) {
            float4 kv = *reinterpret_cast<const float4*>(krow + n);
            float ex = __expf(kv.x), ey = __expf(kv.y);
            float ez = __expf(kv.z), ew = __expf(kv.w);
            if (do_z) z += (ex + ey) + (ez + ew);
            unsigned long long p01, p23;
            PACK2(p01, ex, ey);
            PACK2(p23, ez, ew);
            #pragma unroll
            for (int j = 0; j < 16; j++) {
                const ulonglong2 vv = *reinterpret_cast<const ulonglong2*>(
                    vs + (h * 32 + e0 + j) * CTX_VSL + n);
                FMA2(acc2[j], p01, vv.x);
                FMA2(acc2[j], p23, vv.y);
            }
        }
    }

    float* ctxp = g_ctx + h * (DHEAD * DHEAD) + lane * DHEAD + e0;
    #pragma unroll
    for (int j = 0; j < 16; j++) {
        float lo, hi;
        UNPACK2(lo, hi, acc2[j]);
        atomicAdd(&ctxp[j], lo + hi);
    }
    if (do_z) atomicAdd(&g_z[h * 32 + lane], z);
}

// ---------------- compose M and M2 (exact algebraic folds) ----------------
__global__ void compose_M_kernel(const float* __restrict__ w_out) {
    const int tid = threadIdx.x;
    const int o = blockIdx.x * 2 + (tid >> 7);
    const int c2 = tid & 127;
    const int h = c2 >> 5, d = c2 & 31;
    const float invz = 1.0f / g_z[c2];
    const float* wrow = w_out + o * CDIM + h * 32;
    const float* cr = g_ctx + h * (DHEAD * DHEAD) + d * DHEAD;
    float s = 0.0f;
    #pragma unroll
    for (int e = 0; e < 32; e++) s += wrow[e] * cr[e];
    g_M[o * CDIM + c2] = s * invz;
}
__global__ void compose_M2_kernel(const float* __restrict__ w_qkv,
                                  const float* __restrict__ b_qkv,
                                  const float* __restrict__ b_out) {
    const int tid = threadIdx.x;
    const int o = blockIdx.x * 2 + (tid >> 7);
    const int c = tid & 127;
    const float* mrow = g_M + o * CDIM;
    float s = 0.0f;
    #pragma unroll 8
    for (int j = 0; j < CDIM; j++) s += mrow[j] * w_qkv[j * CDIM + c];
    g_M2[o * CDIM + c] = s;
    if (c == 0) {
        float b = b_out[o];
        #pragma unroll 8
        for (int j = 0; j < CDIM; j++) b += mrow[j] * b_qkv[j];
        g_b2[o] = b;
    }
}

// ---------------- launch ----------------
extern "C" void kernel_launch(void* const* d_in, const int* in_sizes, int n_in,
                              void* d_out, int out_size) {
    const float* x     = (const float*)d_in[0];
    const float* w_qkv = (const float*)d_in[1];
    const float* b_qkv = (const float*)d_in[2];
    const float* w_out = (const float*)d_in[3];
    const float* b_out = (const float*)d_in[4];
    float* y = (float*)d_out;

    const int N = in_sizes[0] / CDIM;     // 147456
    const int tpb = (N / NT) / GRID_G;    // 8
    const int ctx_tiles = N / CTX_TN;

    cudaFuncSetAttribute(gemm_kv_tc,  cudaFuncAttributeMaxDynamicSharedMemorySize, KV_SMEM);
    cudaFuncSetAttribute(gemm_out_tc, cudaFuncAttributeMaxDynamicSharedMemorySize, OUT_SMEM);
    cudaFuncSetAttribute(context_kernel, cudaFuncAttributeMaxDynamicSharedMemorySize, CTX_SMEM);

    zero_small_kernel<<<17, 256>>>();
    prep_w_kernel<<<2, 256>>>(w_qkv);

    // k,v = W_kv @ x + b_kv
    gemm_kv_tc<<<GRID_G, 512, KV_SMEM>>>(x, b_qkv, N, tpb);

    context_kernel<<<296, 256, CTX_SMEM>>>(N, ctx_tiles);
    compose_M_kernel<<<64, 256>>>(w_out);
    compose_M2_kernel<<<64, 256>>>(w_qkv, b_qkv, b_out);
    prep_m2_kernel<<<1, 256>>>();

    // y = M2 @ x + b2
    gemm_out_tc<<<GRID_G, 512, OUT_SMEM>>>(x, y, N, tpb);
}

// round 12
// speedup vs baseline: 3.2524x; 1.5156x over previous
#include <cuda_runtime.h>
#include <cuda_bf16.h>
#include <cstdint>

// Problem constants (fixed by the dataset)
#define HEADS 4
#define DHEAD 32
#define CDIM  128
#define NTOT  147456          // 384*384
#define NT    64              // n-tile width
#define NTILES (NTOT / NT)    // 2304
#define GRID_G 288            // grid.x; tiles-per-block = 8

// ---------------- scratch (static device globals) ----------------
__device__ float g_part[GRID_G * 4096];        // per-block ctx partials [b][h][d][e]
__device__ float g_zpart[GRID_G * 128];        // per-block z partials
__device__ float g_ctx[HEADS * DHEAD * DHEAD]; // reduced context [h][d][e]
__device__ float g_z[CDIM];
__device__ float g_M[CDIM * CDIM];
__device__ float g_M2[CDIM * CDIM];
__device__ float g_b2[CDIM];
__device__ __align__(16) __nv_bfloat16 g_wh[2 * 16384];  // k,v weight hi images [128][128]
__device__ __align__(16) __nv_bfloat16 g_wl[2 * 16384];  // k,v weight lo
__device__ __align__(16) __nv_bfloat16 g_m2h[16384];     // M2 hi
__device__ __align__(16) __nv_bfloat16 g_m2l[16384];     // M2 lo

// ---------------- portable primitives ----------------
__device__ __forceinline__ uint32_t smem_u32(const void* p) {
    uint32_t a;
    asm("{ .reg .u64 t; cvta.to.shared.u64 t, %1; cvt.u32.u64 %0, t; }" : "=r"(a) : "l"(p));
    return a;
}
#define LDM_X4(r0, r1, r2, r3, addr) \
    asm volatile("ldmatrix.sync.aligned.m8n8.x4.shared.b16 {%0,%1,%2,%3}, [%4];" \
                 : "=r"(r0), "=r"(r1), "=r"(r2), "=r"(r3) : "r"(addr))
#define LDM_X4_T(r0, r1, r2, r3, addr) \
    asm volatile("ldmatrix.sync.aligned.m8n8.x4.trans.shared.b16 {%0,%1,%2,%3}, [%4];" \
                 : "=r"(r0), "=r"(r1), "=r"(r2), "=r"(r3) : "r"(addr))
#define MMA16816(d, a0, a1, a2, a3, b0, b1) \
    asm volatile("mma.sync.aligned.m16n8k16.row.col.f32.bf16.bf16.f32 " \
                 "{%0,%1,%2,%3}, {%4,%5,%6,%7}, {%8,%9}, {%0,%1,%2,%3};" \
                 : "+f"((d)[0]), "+f"((d)[1]), "+f"((d)[2]), "+f"((d)[3]) \
                 : "r"(a0), "r"(a1), "r"(a2), "r"(a3), "r"(b0), "r"(b1))

__device__ __forceinline__ uint32_t pack_bf2(float a, float b) {
    __nv_bfloat162 t = __floats2bfloat162_rn(a, b);
    return *reinterpret_cast<uint32_t*>(&t);
}
__device__ __forceinline__ void split_pair(float a, float b, uint32_t& hi, uint32_t& lo) {
    __nv_bfloat16 ha = __float2bfloat16(a), hb = __float2bfloat16(b);
    hi = pack_bf2(__bfloat162float(ha), __bfloat162float(hb));
    lo = pack_bf2(a - __bfloat162float(ha), b - __bfloat162float(hb));
}

// smem geometry
#define LDA  136                       // A image row stride (bf16 elems)
#define CLD  72                        // x/ek/v tile row stride (bf16 elems)
#define A_IMG (128 * LDA * 2)          // 34816 B
#define B_IMG (128 * CLD * 2)          // 18432 B
// fused kv+ctx kernel: AKH | AKL | AVH | AVL | XB_H(=EKH) | XB_L(=EKL) | VH | VL
#define F_XBH (4 * A_IMG)
#define F_XBL (4 * A_IMG + B_IMG)
#define F_VH  (4 * A_IMG + 2 * B_IMG)
#define F_VL  (4 * A_IMG + 3 * B_IMG)
#define F_SMEM (4 * A_IMG + 4 * B_IMG)   // 212992
// out kernel: AH | AL | BH | BL
#define OUT_BH (2 * A_IMG)
#define OUT_BL (2 * A_IMG + B_IMG)
#define OUT_SMEM (2 * A_IMG + 2 * B_IMG)  // 106496

// ---------------- A-image prep: fp32 [128][128] -> dense bf16 hi/lo ----------------
__device__ __forceinline__ void build_a_images(const float* __restrict__ src,
                                               __nv_bfloat16* dh, __nv_bfloat16* dl) {
    const int tid = threadIdx.x;
    for (int c = tid; c < 2048; c += 256) {
        int m = c >> 4, k0 = (c & 15) * 8;
        float4 x0 = *reinterpret_cast<const float4*>(src + m * 128 + k0);
        float4 x1 = *reinterpret_cast<const float4*>(src + m * 128 + k0 + 4);
        float v[8] = {x0.x, x0.y, x0.z, x0.w, x1.x, x1.y, x1.z, x1.w};
        uint32_t h[4], l[4];
        #pragma unroll
        for (int j = 0; j < 4; j++) {
            uint32_t hh, ll;
            split_pair(v[2 * j], v[2 * j + 1], hh, ll);
            h[j] = hh; l[j] = ll;
        }
        *reinterpret_cast<uint4*>(dh + m * 128 + k0) = make_uint4(h[0], h[1], h[2], h[3]);
        *reinterpret_cast<uint4*>(dl + m * 128 + k0) = make_uint4(l[0], l[1], l[2], l[3]);
    }
}
__global__ void prep_w_kernel(const float* __restrict__ w_qkv) {
    int b = blockIdx.x;  // 0 -> k weights (rows 128..255), 1 -> v (rows 256..383)
    build_a_images(w_qkv + (size_t)(1 + b) * 128 * 128, g_wh + b * 16384, g_wl + b * 16384);
}
__global__ void prep_m2_kernel() {
    build_a_images(g_M2, g_m2h, g_m2l);
}

// ---------------- HMMA accumulate over staged smem (main 128x64 GEMM tile) ----------------
__device__ __forceinline__ void mma_tile_acc(
    uint32_t uSM, uint32_t offAh, uint32_t offAl, uint32_t offBh, uint32_t offBl,
    int lane, int wm, int wn, float acc[2][2][4])
{
    #pragma unroll
    for (int i = 0; i < 2; i++)
        #pragma unroll
        for (int j = 0; j < 2; j++)
            #pragma unroll
            for (int r = 0; r < 4; r++) acc[i][j][r] = 0.0f;

    const uint32_t a_row = wm * 32 + (lane & 15);
    const uint32_t a_col = (lane >> 4) * 8;
    const uint32_t b_krow = (lane & 7) + ((lane >> 3) & 1) * 8;
    const uint32_t b_noff = ((lane >> 4) & 1) * 8;

    #pragma unroll
    for (int ks = 0; ks < 8; ks++) {
        uint32_t ah[2][4], al[2][4], bh[4], bl[4];
        #pragma unroll
        for (int i = 0; i < 2; i++) {
            uint32_t off = ((a_row + i * 16) * LDA + ks * 16 + a_col) * 2;
            LDM_X4(ah[i][0], ah[i][1], ah[i][2], ah[i][3], uSM + offAh + off);
            LDM_X4(al[i][0], al[i][1], al[i][2], al[i][3], uSM + offAl + off);
        }
        {
            uint32_t boff = ((ks * 16 + b_krow) * CLD + wn * 16 + b_noff) * 2;
            LDM_X4_T(bh[0], bh[1], bh[2], bh[3], uSM + offBh + boff);
            LDM_X4_T(bl[0], bl[1], bl[2], bl[3], uSM + offBl + boff);
        }
        #pragma unroll
        for (int i = 0; i < 2; i++)
            #pragma unroll
            for (int j = 0; j < 2; j++) {
                MMA16816(acc[i][j], ah[i][0], ah[i][1], ah[i][2], ah[i][3], bh[2*j], bh[2*j+1]);
                MMA16816(acc[i][j], ah[i][0], ah[i][1], ah[i][2], ah[i][3], bl[2*j], bl[2*j+1]);
                MMA16816(acc[i][j], al[i][0], al[i][1], al[i][2], al[i][3], bh[2*j], bh[2*j+1]);
            }
    }
}

__device__ __forceinline__ void store_acc(
    float* __restrict__ out, int N, int col0, int wm, int wn, int lane,
    const float acc[2][2][4], const float* __restrict__ bias)
{
    #pragma unroll
    for (int i = 0; i < 2; i++) {
        const int row = wm * 32 + i * 16 + (lane >> 2);
        const float b0 = bias[row], b1 = bias[row + 8];
        #pragma unroll
        for (int j = 0; j < 2; j++) {
            const int col = col0 + wn * 16 + j * 8 + (lane & 3) * 2;
            *reinterpret_cast<float2*>(out + (size_t)row * N + col) =
                make_float2(acc[i][j][0] + b0, acc[i][j][1] + b0);
            *reinterpret_cast<float2*>(out + (size_t)(row + 8) * N + col) =
                make_float2(acc[i][j][2] + b1, acc[i][j][3] + b1);
        }
    }
}

// load x tile [128c][64n] fp32 into 4 float4 regs (512 threads)
__device__ __forceinline__ void ldg_tile(float4 pf[4], const float* __restrict__ x,
                                         int N, int n0, int tid) {
    #pragma unroll
    for (int i = 0; i < 4; i++) {
        int idx = tid + i * 512, r = idx >> 4, q = idx & 15;
        pf[i] = *reinterpret_cast<const float4*>(x + (size_t)r * N + n0 + q * 4);
    }
}
// convert regs -> bf16 hi/lo smem tiles
__device__ __forceinline__ void sts_convert(const float4 pf[4], char* sm,
                                            uint32_t offBh, uint32_t offBl, int tid) {
    #pragma unroll
    for (int i = 0; i < 4; i++) {
        int idx = tid + i * 512, r = idx >> 4, q = idx & 15;
        float4 v = pf[i];
        uint2 hp, lp;
        split_pair(v.x, v.y, hp.x, lp.x);
        split_pair(v.z, v.w, hp.y, lp.y);
        *reinterpret_cast<uint2*>(sm + offBh + (r * CLD + q * 4) * 2) = hp;
        *reinterpret_cast<uint2*>(sm + offBl + (r * CLD + q * 4) * 2) = lp;
    }
}

// ---------------- FUSED: k,v GEMM + exp + block-diagonal context accumulation ----------------
__global__ void __launch_bounds__(512, 1)
gemm_kv_ctx(const float* __restrict__ x, const float* __restrict__ b_qkv, int N, int tpb) {
    extern __shared__ __align__(16) char sm[];
    __shared__ float zbuf[128];
    const int tid = threadIdx.x, lane = tid & 31, w = tid >> 5;
    const int wm = w & 3, wn = w >> 2;
    const uint32_t uSM = smem_u32(sm);

    // ctx warp mapping: head = w&3, quadrant = w>>2 -> (d-half, e-half)
    const int chead = w & 3, cq = w >> 2;
    const int dhalf = cq & 1, ehalf = cq >> 1;

    // stage 4 weight images (kh, kl, vh, vl)
    for (int i = tid; i < 8192; i += 512) {
        int img = i >> 11, rem = i & 2047, r = rem >> 4, q = rem & 15;
        int set = img >> 1;
        const __nv_bfloat16* srcb = (img & 1) ? g_wl : g_wh;
        uint4 v = reinterpret_cast<const uint4*>(srcb + set * 16384 + r * 128)[q];
        *reinterpret_cast<uint4*>(sm + img * A_IMG + (r * LDA + q * 8) * 2) = v;
    }
    if (tid < 128) zbuf[tid] = 0.0f;

    // per-thread biases for the 4 owned k rows and 4 owned v rows
    float bk[4], bv[4];
    #pragma unroll
    for (int i = 0; i < 2; i++) {
        int r0 = wm * 32 + i * 16 + (lane >> 2);
        bk[2 * i] = b_qkv[128 + r0];      bk[2 * i + 1] = b_qkv[128 + r0 + 8];
        bv[2 * i] = b_qkv[256 + r0];      bv[2 * i + 1] = b_qkv[256 + r0 + 8];
    }

    float accc[2][4];   // persistent ctx accumulators (1 m16 x 2 n8)
    #pragma unroll
    for (int j = 0; j < 2; j++)
        #pragma unroll
        for (int r = 0; r < 4; r++) accc[j][r] = 0.0f;
    float zth[4] = {0.f, 0.f, 0.f, 0.f};

    int t = blockIdx.x;
    float4 pf[4];
    ldg_tile(pf, x, N, t * NT, tid);
    __syncthreads();

    for (int it = 0; it < tpb; it++, t += GRID_G) {
        // 1) stage x tile (hi/lo) into XB region
        sts_convert(pf, sm, F_XBH, F_XBL, tid);
        __syncthreads();
        // 2) prefetch next x tile
        if (it + 1 < tpb) ldg_tile(pf, x, N, (t + GRID_G) * NT, tid);

        // 3) k and v MMAs (A = weight images, B = x tile)
        float acck[2][2][4], accv[2][2][4];
        mma_tile_acc(uSM, 0, A_IMG, F_XBH, F_XBL, lane, wm, wn, acck);
        mma_tile_acc(uSM, 2 * A_IMG, 3 * A_IMG, F_XBH, F_XBL, lane, wm, wn, accv);
        __syncthreads();   // all warps done reading XB (x)

        // 4) write ek = exp(k+bias) into XB region (hi/lo), v+bias into V region; accumulate z
        #pragma unroll
        for (int i = 0; i < 2; i++) {
            const int r0 = wm * 32 + i * 16 + (lane >> 2), r1 = r0 + 8;
            #pragma unroll
            for (int j = 0; j < 2; j++) {
                const int col = wn * 16 + j * 8 + (lane & 3) * 2;
                // ek rows
                float e00 = __expf(acck[i][j][0] + bk[2 * i]);
                float e01 = __expf(acck[i][j][1] + bk[2 * i]);
                float e10 = __expf(acck[i][j][2] + bk[2 * i + 1]);
                float e11 = __expf(acck[i][j][3] + bk[2 * i + 1]);
                zth[2 * i]     += e00 + e01;
                zth[2 * i + 1] += e10 + e11;
                uint32_t h0, l0, h1, l1;
                split_pair(e00, e01, h0, l0);
                split_pair(e10, e11, h1, l1);
                *reinterpret_cast<uint32_t*>(sm + F_XBH + (r0 * CLD + col) * 2) = h0;
                *reinterpret_cast<uint32_t*>(sm + F_XBL + (r0 * CLD + col) * 2) = l0;
                *reinterpret_cast<uint32_t*>(sm + F_XBH + (r1 * CLD + col) * 2) = h1;
                *reinterpret_cast<uint32_t*>(sm + F_XBL + (r1 * CLD + col) * 2) = l1;
                // v rows
                float v00 = accv[i][j][0] + bv[2 * i];
                float v01 = accv[i][j][1] + bv[2 * i];
                float v10 = accv[i][j][2] + bv[2 * i + 1];
                float v11 = accv[i][j][3] + bv[2 * i + 1];
                split_pair(v00, v01, h0, l0);
                split_pair(v10, v11, h1, l1);
                *reinterpret_cast<uint32_t*>(sm + F_VH + (r0 * CLD + col) * 2) = h0;
                *reinterpret_cast<uint32_t*>(sm + F_VL + (r0 * CLD + col) * 2) = l0;
                *reinterpret_cast<uint32_t*>(sm + F_VH + (r1 * CLD + col) * 2) = h1;
                *reinterpret_cast<uint32_t*>(sm + F_VL + (r1 * CLD + col) * 2) = l1;
            }
        }
        __syncthreads();   // ek/v tiles complete

        // 5) block-diagonal ctx MMA: ctx[h][d][e] += ek[h*32+d, n] * v[h*32+e, n]
        //    A = ek rows [chead*32 + dhalf*16 .. +16), K = n (4 chunks of 16)
        //    B = v rows  [chead*32 + ehalf*16 .. +16) (N-major storage, non-trans ldmatrix)
        {
            const uint32_t arow = chead * 32 + dhalf * 16 + (lane & 15);
            const uint32_t erow = chead * 32 + ehalf * 16 + (lane & 15);
            const uint32_t ksub = (lane >> 4) * 8;
            #pragma unroll
            for (int ks = 0; ks < 4; ks++) {
                uint32_t eh[4], el[4], vh4[4], vl4[4];
                uint32_t aoff = (arow * CLD + ks * 16 + ksub) * 2;
                uint32_t boff = (erow * CLD + ks * 16 + ksub) * 2;
                LDM_X4(eh[0], eh[1], eh[2], eh[3], uSM + F_XBH + aoff);
                LDM_X4(el[0], el[1], el[2], el[3], uSM + F_XBL + aoff);
                LDM_X4(vh4[0], vh4[1], vh4[2], vh4[3], uSM + F_VH + boff);
                LDM_X4(vl4[0], vl4[1], vl4[2], vl4[3], uSM + F_VL + boff);
                #pragma unroll
                for (int j = 0; j < 2; j++) {
                    MMA16816(accc[j], eh[0], eh[1], eh[2], eh[3], vh4[j], vh4[j + 2]);
                    MMA16816(accc[j], eh[0], eh[1], eh[2], eh[3], vl4[j], vl4[j + 2]);
                    MMA16816(accc[j], el[0], el[1], el[2], el[3], vh4[j], vh4[j + 2]);
                }
            }
        }
        __syncthreads();   // ctx phase done; XB/V free for next iteration
    }

    // ---- write ctx partials: g_part[b][h*1024 + d*32 + e] ----
    {
        float* part = g_part + (size_t)blockIdx.x * 4096 + chead * 1024;
        const int dloc0 = dhalf * 16 + (lane >> 2);
        #pragma unroll
        for (int j = 0; j < 2; j++) {
            const int eloc = ehalf * 16 + j * 8 + (lane & 3) * 2;
            *reinterpret_cast<float2*>(part + dloc0 * 32 + eloc) =
                make_float2(accc[j][0], accc[j][1]);
            *reinterpret_cast<float2*>(part + (dloc0 + 8) * 32 + eloc) =
                make_float2(accc[j][2], accc[j][3]);
        }
    }
    // ---- z partials: reduce 4 lanes sharing a row, then smem, then global ----
    #pragma unroll
    for (int c = 0; c < 4; c++) {
        zth[c] += __shfl_xor_sync(0xffffffffu, zth[c], 1);
        zth[c] += __shfl_xor_sync(0xffffffffu, zth[c], 2);
    }
    if ((lane & 3) == 0) {
        #pragma unroll
        for (int c = 0; c < 4; c++) {
            int row = wm * 32 + (c >> 1) * 16 + (lane >> 2) + (c & 1) * 8;
            atomicAdd(&zbuf[row], zth[c]);
        }
    }
    __syncthreads();
    if (tid < 128) g_zpart[blockIdx.x * 128 + tid] = zbuf[tid];
}

// ---------------- reduce partials -> ctx, z ----------------
__global__ void reduce_ctx_kernel() {
    int i = blockIdx.x * blockDim.x + threadIdx.x;   // 0..4095
    float s = 0.0f;
    for (int b = 0; b < GRID_G; b++) s += g_part[b * 4096 + i];
    g_ctx[i] = s;
    if (i < 128) {
        float z = 0.0f;
        for (int b = 0; b < GRID_G; b++) z += g_zpart[b * 128 + i];
        g_z[i] = z;
    }
}

// ---------------- GEMM 2: y = M2 @ x + b2 ----------------
__global__ void __launch_bounds__(512, 2)
gemm_out_tc(const float* __restrict__ x, float* __restrict__ y, int N, int tpb) {
    extern __shared__ __align__(16) char sm[];
    const int tid = threadIdx.x, lane = tid & 31, w = tid >> 5;
    const int wm = w & 3, wn = w >> 2;
    const uint32_t uSM = smem_u32(sm);

    for (int i = tid; i < 4096; i += 512) {
        int img = i >> 11, rem = i & 2047, r = rem >> 4, q = rem & 15;
        const __nv_bfloat16* srcb = img ? g_m2l : g_m2h;
        uint4 v = reinterpret_cast<const uint4*>(srcb + r * 128)[q];
        *reinterpret_cast<uint4*>(sm + img * A_IMG + (r * LDA + q * 8) * 2) = v;
    }

    int t = blockIdx.x;
    float4 pf[4];
    ldg_tile(pf, x, N, t * NT, tid);
    __syncthreads();

    for (int it = 0; it < tpb; it++, t += GRID_G) {
        sts_convert(pf, sm, OUT_BH, OUT_BL, tid);
        __syncthreads();
        if (it + 1 < tpb) ldg_tile(pf, x, N, (t + GRID_G) * NT, tid);

        float acc[2][2][4];
        mma_tile_acc(uSM, 0, A_IMG, OUT_BH, OUT_BL, lane, wm, wn, acc);
        store_acc(y, N, t * NT, wm, wn, lane, acc, g_b2);
        __syncthreads();
    }
}

// ---------------- compose M and M2 (exact algebraic folds) ----------------
__global__ void compose_M_kernel(const float* __restrict__ w_out) {
    const int tid = threadIdx.x;
    const int o = blockIdx.x * 2 + (tid >> 7);
    const int c2 = tid & 127;
    const int h = c2 >> 5, d = c2 & 31;
    const float invz = 1.0f / g_z[c2];
    const float* wrow = w_out + o * CDIM + h * 32;
    const float* cr = g_ctx + h * (DHEAD * DHEAD) + d * DHEAD;
    float s = 0.0f;
    #pragma unroll
    for (int e = 0; e < 32; e++) s += wrow[e] * cr[e];
    g_M[o * CDIM + c2] = s * invz;
}
__global__ void compose_M2_kernel(const float* __restrict__ w_qkv,
                                  const float* __restrict__ b_qkv,
                                  const float* __restrict__ b_out) {
    const int tid = threadIdx.x;
    const int o = blockIdx.x * 2 + (tid >> 7);
    const int c = tid & 127;
    const float* mrow = g_M + o * CDIM;
    float s = 0.0f;
    #pragma unroll 8
    for (int j = 0; j < CDIM; j++) s += mrow[j] * w_qkv[j * CDIM + c];
    g_M2[o * CDIM + c] = s;
    if (c == 0) {
        float b = b_out[o];
        #pragma unroll 8
        for (int j = 0; j < CDIM; j++) b += mrow[j] * b_qkv[j];
        g_b2[o] = b;
    }
}

// ---------------- launch ----------------
extern "C" void kernel_launch(void* const* d_in, const int* in_sizes, int n_in,
                              void* d_out, int out_size) {
    const float* x     = (const float*)d_in[0];
    const float* w_qkv = (const float*)d_in[1];
    const float* b_qkv = (const float*)d_in[2];
    const float* w_out = (const float*)d_in[3];
    const float* b_out = (const float*)d_in[4];
    float* y = (float*)d_out;

    const int N = in_sizes[0] / CDIM;     // 147456
    const int tpb = (N / NT) / GRID_G;    // 8

    cudaFuncSetAttribute(gemm_kv_ctx, cudaFuncAttributeMaxDynamicSharedMemorySize, F_SMEM);
    cudaFuncSetAttribute(gemm_out_tc, cudaFuncAttributeMaxDynamicSharedMemorySize, OUT_SMEM);

    // 1) weight bf16 hi/lo images
    prep_w_kernel<<<2, 256>>>(w_qkv);

    // 2) fused: k,v projection + exp + block-diagonal context partials
    gemm_kv_ctx<<<GRID_G, 512, F_SMEM>>>(x, b_qkv, N, tpb);

    // 3) reduce partials -> ctx, z
    reduce_ctx_kernel<<<16, 256>>>();

    // 4) exact folds: M = W_out*blockdiag(ctx^T/Z); M2 = M*W_q; b2 = M*b_q + b_out
    compose_M_kernel<<<64, 256>>>(w_out);
    compose_M2_kernel<<<64, 256>>>(w_qkv, b_qkv, b_out);
    prep_m2_kernel<<<1, 256>>>();

    // 5) y = M2 @ x + b2
    gemm_out_tc<<<GRID_G, 512, OUT_SMEM>>>(x, y, N, tpb);
}

// round 13
// speedup vs baseline: 3.5123x; 1.0799x over previous
#include <cuda_runtime.h>
#include <cuda_bf16.h>
#include <cstdint>

// Problem constants (fixed by the dataset)
#define HEADS 4
#define DHEAD 32
#define CDIM  128
#define NTOT  147456          // 384*384
#define NT    64              // n-tile width
#define NTILES (NTOT / NT)    // 2304
#define GRID_KV 144           // kv grid: 1 wave at 1 CTA/SM; tpb = 16
#define GRID_OUT 288          // out grid: 1 wave at 2 CTA/SM; tpb = 8

// ---------------- scratch (static device globals) ----------------
__device__ float g_part[GRID_KV * 4096];       // per-block ctx partials [b][h][d][e]
__device__ float g_zpart[GRID_KV * 128];       // per-block z partials
__device__ float g_ctx[HEADS * DHEAD * DHEAD]; // reduced context [h][d][e]
__device__ float g_z[CDIM];
__device__ float g_M[CDIM * CDIM];
__device__ float g_M2[CDIM * CDIM];
__device__ float g_b2[CDIM];

// ---------------- portable primitives ----------------
__device__ __forceinline__ uint32_t smem_u32(const void* p) {
    uint32_t a;
    asm("{ .reg .u64 t; cvta.to.shared.u64 t, %1; cvt.u32.u64 %0, t; }" : "=r"(a) : "l"(p));
    return a;
}
#define LDM_X4(r0, r1, r2, r3, addr) \
    asm volatile("ldmatrix.sync.aligned.m8n8.x4.shared.b16 {%0,%1,%2,%3}, [%4];" \
                 : "=r"(r0), "=r"(r1), "=r"(r2), "=r"(r3) : "r"(addr))
#define LDM_X4_T(r0, r1, r2, r3, addr) \
    asm volatile("ldmatrix.sync.aligned.m8n8.x4.trans.shared.b16 {%0,%1,%2,%3}, [%4];" \
                 : "=r"(r0), "=r"(r1), "=r"(r2), "=r"(r3) : "r"(addr))
#define MMA16816(d, a0, a1, a2, a3, b0, b1) \
    asm volatile("mma.sync.aligned.m16n8k16.row.col.f32.bf16.bf16.f32 " \
                 "{%0,%1,%2,%3}, {%4,%5,%6,%7}, {%8,%9}, {%0,%1,%2,%3};" \
                 : "+f"((d)[0]), "+f"((d)[1]), "+f"((d)[2]), "+f"((d)[3]) \
                 : "r"(a0), "r"(a1), "r"(a2), "r"(a3), "r"(b0), "r"(b1))

__device__ __forceinline__ uint32_t pack_bf2(float a, float b) {
    __nv_bfloat162 t = __floats2bfloat162_rn(a, b);
    return *reinterpret_cast<uint32_t*>(&t);
}
__device__ __forceinline__ void split_pair(float a, float b, uint32_t& hi, uint32_t& lo) {
    __nv_bfloat16 ha = __float2bfloat16(a), hb = __float2bfloat16(b);
    hi = pack_bf2(__bfloat162float(ha), __bfloat162float(hb));
    lo = pack_bf2(a - __bfloat162float(ha), b - __bfloat162float(hb));
}

// smem geometry
#define LDA  136                       // A image row stride (bf16 elems)
#define CLD  72                        // x/ek/v tile row stride (bf16 elems)
#define A_IMG (128 * LDA * 2)          // 34816 B
#define B_IMG (128 * CLD * 2)          // 18432 B
// fused kv+ctx kernel: AKH | AKL | AVH | AVL | XB_H(=EKH) | XB_L(=EKL) | VH | VL
#define F_XBH (4 * A_IMG)
#define F_XBL (4 * A_IMG + B_IMG)
#define F_VH  (4 * A_IMG + 2 * B_IMG)
#define F_VL  (4 * A_IMG + 3 * B_IMG)
#define F_SMEM (4 * A_IMG + 4 * B_IMG)   // 212992
// out kernel: AH | AL | BH | BL
#define OUT_BH (2 * A_IMG)
#define OUT_BL (2 * A_IMG + B_IMG)
#define OUT_SMEM (2 * A_IMG + 2 * B_IMG)  // 106496

// ---------------- HMMA accumulate over staged smem (generic 128x64 tile) ----------------
__device__ __forceinline__ void mma_tile_acc(
    uint32_t uSM, uint32_t offAh, uint32_t offAl, uint32_t offBh, uint32_t offBl,
    int lane, int wm, int wn, float acc[2][2][4])
{
    #pragma unroll
    for (int i = 0; i < 2; i++)
        #pragma unroll
        for (int j = 0; j < 2; j++)
            #pragma unroll
            for (int r = 0; r < 4; r++) acc[i][j][r] = 0.0f;

    const uint32_t a_row = wm * 32 + (lane & 15);
    const uint32_t a_col = (lane >> 4) * 8;
    const uint32_t b_krow = (lane & 7) + ((lane >> 3) & 1) * 8;
    const uint32_t b_noff = ((lane >> 4) & 1) * 8;

    #pragma unroll
    for (int ks = 0; ks < 8; ks++) {
        uint32_t ah[2][4], al[2][4], bh[4], bl[4];
        #pragma unroll
        for (int i = 0; i < 2; i++) {
            uint32_t off = ((a_row + i * 16) * LDA + ks * 16 + a_col) * 2;
            LDM_X4(ah[i][0], ah[i][1], ah[i][2], ah[i][3], uSM + offAh + off);
            LDM_X4(al[i][0], al[i][1], al[i][2], al[i][3], uSM + offAl + off);
        }
        {
            uint32_t boff = ((ks * 16 + b_krow) * CLD + wn * 16 + b_noff) * 2;
            LDM_X4_T(bh[0], bh[1], bh[2], bh[3], uSM + offBh + boff);
            LDM_X4_T(bl[0], bl[1], bl[2], bl[3], uSM + offBl + boff);
        }
        #pragma unroll
        for (int i = 0; i < 2; i++)
            #pragma unroll
            for (int j = 0; j < 2; j++) {
                MMA16816(acc[i][j], ah[i][0], ah[i][1], ah[i][2], ah[i][3], bh[2*j], bh[2*j+1]);
                MMA16816(acc[i][j], ah[i][0], ah[i][1], ah[i][2], ah[i][3], bl[2*j], bl[2*j+1]);
                MMA16816(acc[i][j], al[i][0], al[i][1], al[i][2], al[i][3], bh[2*j], bh[2*j+1]);
            }
    }
}

__device__ __forceinline__ void store_acc(
    float* __restrict__ out, int N, int col0, int wm, int wn, int lane,
    const float acc[2][2][4], const float* __restrict__ bias)
{
    #pragma unroll
    for (int i = 0; i < 2; i++) {
        const int row = wm * 32 + i * 16 + (lane >> 2);
        const float b0 = bias[row], b1 = bias[row + 8];
        #pragma unroll
        for (int j = 0; j < 2; j++) {
            const int col = col0 + wn * 16 + j * 8 + (lane & 3) * 2;
            *reinterpret_cast<float2*>(out + (size_t)row * N + col) =
                make_float2(acc[i][j][0] + b0, acc[i][j][1] + b0);
            *reinterpret_cast<float2*>(out + (size_t)(row + 8) * N + col) =
                make_float2(acc[i][j][2] + b1, acc[i][j][3] + b1);
        }
    }
}

// load x tile [128c][64n] fp32 into 4 float4 regs (512 threads)
__device__ __forceinline__ void ldg_tile(float4 pf[4], const float* __restrict__ x,
                                         int N, int n0, int tid) {
    #pragma unroll
    for (int i = 0; i < 4; i++) {
        int idx = tid + i * 512, r = idx >> 4, q = idx & 15;
        pf[i] = *reinterpret_cast<const float4*>(x + (size_t)r * N + n0 + q * 4);
    }
}
// convert regs -> bf16 hi/lo smem tiles
__device__ __forceinline__ void sts_convert(const float4 pf[4], char* sm,
                                            uint32_t offBh, uint32_t offBl, int tid) {
    #pragma unroll
    for (int i = 0; i < 4; i++) {
        int idx = tid + i * 512, r = idx >> 4, q = idx & 15;
        float4 v = pf[i];
        uint2 hp, lp;
        split_pair(v.x, v.y, hp.x, lp.x);
        split_pair(v.z, v.w, hp.y, lp.y);
        *reinterpret_cast<uint2*>(sm + offBh + (r * CLD + q * 4) * 2) = hp;
        *reinterpret_cast<uint2*>(sm + offBl + (r * CLD + q * 4) * 2) = lp;
    }
}

// ---------------- FUSED: k,v GEMM + exp + block-diagonal context accumulation ----------------
__global__ void __launch_bounds__(512, 1)
gemm_kv_ctx(const float* __restrict__ x, const float* __restrict__ w_qkv,
            const float* __restrict__ b_qkv, int N, int tpb) {
    extern __shared__ __align__(16) char sm[];
    __shared__ float zbuf[128];
    const int tid = threadIdx.x, lane = tid & 31, w = tid >> 5;
    const int wm = w & 3, wn = w >> 2;
    const uint32_t uSM = smem_u32(sm);

    // ctx warp mapping: head = w&3, quadrant = w>>2 -> (d-half, e-half)
    const int chead = w & 3, cq = w >> 2;
    const int dhalf = cq & 1, ehalf = cq >> 1;

    // stage 4 weight images directly from w_qkv (convert fp32 -> bf16 hi/lo in-block)
    // source rows 128..383: set 0 = k, set 1 = v; images: kh(0) kl(1) vh(2) vl(3)
    for (int i = tid; i < 8192; i += 512) {
        int r = i >> 5;          // 0..255
        int q = i & 31;          // float4 col (4 elems)
        float4 v = *reinterpret_cast<const float4*>(w_qkv + (size_t)(128 + r) * 128 + q * 4);
        uint2 hp, lp;
        split_pair(v.x, v.y, hp.x, lp.x);
        split_pair(v.z, v.w, hp.y, lp.y);
        int set = r >> 7, rr = r & 127;
        *reinterpret_cast<uint2*>(sm + (set * 2 + 0) * A_IMG + (rr * LDA + q * 4) * 2) = hp;
        *reinterpret_cast<uint2*>(sm + (set * 2 + 1) * A_IMG + (rr * LDA + q * 4) * 2) = lp;
    }
    if (tid < 128) zbuf[tid] = 0.0f;

    // per-thread biases for the 4 owned k rows and 4 owned v rows
    float bk[4], bv[4];
    #pragma unroll
    for (int i = 0; i < 2; i++) {
        int r0 = wm * 32 + i * 16 + (lane >> 2);
        bk[2 * i] = b_qkv[128 + r0];      bk[2 * i + 1] = b_qkv[128 + r0 + 8];
        bv[2 * i] = b_qkv[256 + r0];      bv[2 * i + 1] = b_qkv[256 + r0 + 8];
    }

    float accc[2][4];   // persistent ctx accumulators (1 m16 x 2 n8)
    #pragma unroll
    for (int j = 0; j < 2; j++)
        #pragma unroll
        for (int r = 0; r < 4; r++) accc[j][r] = 0.0f;
    float zth[4] = {0.f, 0.f, 0.f, 0.f};

    int t = blockIdx.x;
    float4 pf[4];
    ldg_tile(pf, x, N, t * NT, tid);
    __syncthreads();

    // fragment address components (main GEMM)
    const uint32_t a_row = wm * 32 + (lane & 15);
    const uint32_t a_col = (lane >> 4) * 8;
    const uint32_t b_krow = (lane & 7) + ((lane >> 3) & 1) * 8;
    const uint32_t b_noff = ((lane >> 4) & 1) * 8;

    for (int it = 0; it < tpb; it++, t += GRID_KV) {
        // 1) stage x tile (hi/lo) into XB region
        sts_convert(pf, sm, F_XBH, F_XBL, tid);
        __syncthreads();
        // 2) prefetch next x tile
        if (it + 1 < tpb) ldg_tile(pf, x, N, (t + GRID_KV) * NT, tid);

        // 3) fused k+v MMAs sharing one B-fragment load per ks
        float acck[2][2][4], accv[2][2][4];
        #pragma unroll
        for (int i = 0; i < 2; i++)
            #pragma unroll
            for (int j = 0; j < 2; j++)
                #pragma unroll
                for (int r = 0; r < 4; r++) { acck[i][j][r] = 0.0f; accv[i][j][r] = 0.0f; }

        #pragma unroll
        for (int ks = 0; ks < 8; ks++) {
            uint32_t bh[4], bl[4];
            {
                uint32_t boff = ((ks * 16 + b_krow) * CLD + wn * 16 + b_noff) * 2;
                LDM_X4_T(bh[0], bh[1], bh[2], bh[3], uSM + F_XBH + boff);
                LDM_X4_T(bl[0], bl[1], bl[2], bl[3], uSM + F_XBL + boff);
            }
            #pragma unroll
            for (int i = 0; i < 2; i++) {
                uint32_t off = ((a_row + i * 16) * LDA + ks * 16 + a_col) * 2;
                uint32_t ah[4], al[4];
                LDM_X4(ah[0], ah[1], ah[2], ah[3], uSM + 0 * A_IMG + off);  // kh
                LDM_X4(al[0], al[1], al[2], al[3], uSM + 1 * A_IMG + off);  // kl
                #pragma unroll
                for (int j = 0; j < 2; j++) {
                    MMA16816(acck[i][j], ah[0], ah[1], ah[2], ah[3], bh[2*j], bh[2*j+1]);
                    MMA16816(acck[i][j], ah[0], ah[1], ah[2], ah[3], bl[2*j], bl[2*j+1]);
                    MMA16816(acck[i][j], al[0], al[1], al[2], al[3], bh[2*j], bh[2*j+1]);
                }
                LDM_X4(ah[0], ah[1], ah[2], ah[3], uSM + 2 * A_IMG + off);  // vh
                LDM_X4(al[0], al[1], al[2], al[3], uSM + 3 * A_IMG + off);  // vl
                #pragma unroll
                for (int j = 0; j < 2; j++) {
                    MMA16816(accv[i][j], ah[0], ah[1], ah[2], ah[3], bh[2*j], bh[2*j+1]);
                    MMA16816(accv[i][j], ah[0], ah[1], ah[2], ah[3], bl[2*j], bl[2*j+1]);
                    MMA16816(accv[i][j], al[0], al[1], al[2], al[3], bh[2*j], bh[2*j+1]);
                }
            }
        }
        __syncthreads();   // all warps done reading XB (x)

        // 4) write ek = exp(k+bias) into XB region (hi/lo), v+bias into V region; accumulate z
        #pragma unroll
        for (int i = 0; i < 2; i++) {
            const int r0 = wm * 32 + i * 16 + (lane >> 2), r1 = r0 + 8;
            #pragma unroll
            for (int j = 0; j < 2; j++) {
                const int col = wn * 16 + j * 8 + (lane & 3) * 2;
                float e00 = __expf(acck[i][j][0] + bk[2 * i]);
                float e01 = __expf(acck[i][j][1] + bk[2 * i]);
                float e10 = __expf(acck[i][j][2] + bk[2 * i + 1]);
                float e11 = __expf(acck[i][j][3] + bk[2 * i + 1]);
                zth[2 * i]     += e00 + e01;
                zth[2 * i + 1] += e10 + e11;
                uint32_t h0, l0, h1, l1;
                split_pair(e00, e01, h0, l0);
                split_pair(e10, e11, h1, l1);
                *reinterpret_cast<uint32_t*>(sm + F_XBH + (r0 * CLD + col) * 2) = h0;
                *reinterpret_cast<uint32_t*>(sm + F_XBL + (r0 * CLD + col) * 2) = l0;
                *reinterpret_cast<uint32_t*>(sm + F_XBH + (r1 * CLD + col) * 2) = h1;
                *reinterpret_cast<uint32_t*>(sm + F_XBL + (r1 * CLD + col) * 2) = l1;
                float v00 = accv[i][j][0] + bv[2 * i];
                float v01 = accv[i][j][1] + bv[2 * i];
                float v10 = accv[i][j][2] + bv[2 * i + 1];
                float v11 = accv[i][j][3] + bv[2 * i + 1];
                split_pair(v00, v01, h0, l0);
                split_pair(v10, v11, h1, l1);
                *reinterpret_cast<uint32_t*>(sm + F_VH + (r0 * CLD + col) * 2) = h0;
                *reinterpret_cast<uint32_t*>(sm + F_VL + (r0 * CLD + col) * 2) = l0;
                *reinterpret_cast<uint32_t*>(sm + F_VH + (r1 * CLD + col) * 2) = h1;
                *reinterpret_cast<uint32_t*>(sm + F_VL + (r1 * CLD + col) * 2) = l1;
            }
        }
        __syncthreads();   // ek/v tiles complete

        // 5) block-diagonal ctx MMA: ctx[h][d][e] += ek[h*32+d, n] * v[h*32+e, n]
        {
            const uint32_t arow = chead * 32 + dhalf * 16 + (lane & 15);
            const uint32_t erow = chead * 32 + ehalf * 16 + (lane & 15);
            const uint32_t ksub = (lane >> 4) * 8;
            #pragma unroll
            for (int ks = 0; ks < 4; ks++) {
                uint32_t eh[4], el[4], vh4[4], vl4[4];
                uint32_t aoff = (arow * CLD + ks * 16 + ksub) * 2;
                uint32_t boff = (erow * CLD + ks * 16 + ksub) * 2;
                LDM_X4(eh[0], eh[1], eh[2], eh[3], uSM + F_XBH + aoff);
                LDM_X4(el[0], el[1], el[2], el[3], uSM + F_XBL + aoff);
                LDM_X4(vh4[0], vh4[1], vh4[2], vh4[3], uSM + F_VH + boff);
                LDM_X4(vl4[0], vl4[1], vl4[2], vl4[3], uSM + F_VL + boff);
                #pragma unroll
                for (int j = 0; j < 2; j++) {
                    MMA16816(accc[j], eh[0], eh[1], eh[2], eh[3], vh4[j], vh4[j + 2]);
                    MMA16816(accc[j], eh[0], eh[1], eh[2], eh[3], vl4[j], vl4[j + 2]);
                    MMA16816(accc[j], el[0], el[1], el[2], el[3], vh4[j], vh4[j + 2]);
                }
            }
        }
        __syncthreads();   // ctx phase done; XB/V free for next iteration
    }

    // ---- write ctx partials: g_part[b][h*1024 + d*32 + e] ----
    {
        float* part = g_part + (size_t)blockIdx.x * 4096 + chead * 1024;
        const int dloc0 = dhalf * 16 + (lane >> 2);
        #pragma unroll
        for (int j = 0; j < 2; j++) {
            const int eloc = ehalf * 16 + j * 8 + (lane & 3) * 2;
            *reinterpret_cast<float2*>(part + dloc0 * 32 + eloc) =
                make_float2(accc[j][0], accc[j][1]);
            *reinterpret_cast<float2*>(part + (dloc0 + 8) * 32 + eloc) =
                make_float2(accc[j][2], accc[j][3]);
        }
    }
    // ---- z partials ----
    #pragma unroll
    for (int c = 0; c < 4; c++) {
        zth[c] += __shfl_xor_sync(0xffffffffu, zth[c], 1);
        zth[c] += __shfl_xor_sync(0xffffffffu, zth[c], 2);
    }
    if ((lane & 3) == 0) {
        #pragma unroll
        for (int c = 0; c < 4; c++) {
            int row = wm * 32 + (c >> 1) * 16 + (lane >> 2) + (c & 1) * 8;
            atomicAdd(&zbuf[row], zth[c]);
        }
    }
    __syncthreads();
    if (tid < 128) g_zpart[blockIdx.x * 128 + tid] = zbuf[tid];
}

// ---------------- reduce partials -> ctx, z ----------------
__global__ void reduce_ctx_kernel() {
    int i = blockIdx.x * blockDim.x + threadIdx.x;   // 0..4095
    float s = 0.0f;
    for (int b = 0; b < GRID_KV; b++) s += g_part[b * 4096 + i];
    g_ctx[i] = s;
    if (i < 128) {
        float z = 0.0f;
        for (int b = 0; b < GRID_KV; b++) z += g_zpart[b * 128 + i];
        g_z[i] = z;
    }
}

// ---------------- GEMM 2: y = M2 @ x + b2 (M2 converted in-block) ----------------
__global__ void __launch_bounds__(512, 2)
gemm_out_tc(const float* __restrict__ x, float* __restrict__ y, int N, int tpb) {
    extern __shared__ __align__(16) char sm[];
    const int tid = threadIdx.x, lane = tid & 31, w = tid >> 5;
    const int wm = w & 3, wn = w >> 2;
    const uint32_t uSM = smem_u32(sm);

    // convert M2 fp32 [128][128] -> bf16 hi/lo images in smem
    for (int i = tid; i < 4096; i += 512) {
        int r = i >> 5, q = i & 31;
        float4 v = *reinterpret_cast<const float4*>(g_M2 + r * 128 + q * 4);
        uint2 hp, lp;
        split_pair(v.x, v.y, hp.x, lp.x);
        split_pair(v.z, v.w, hp.y, lp.y);
        *reinterpret_cast<uint2*>(sm + 0 * A_IMG + (r * LDA + q * 4) * 2) = hp;
        *reinterpret_cast<uint2*>(sm + 1 * A_IMG + (r * LDA + q * 4) * 2) = lp;
    }

    int t = blockIdx.x;
    float4 pf[4];
    ldg_tile(pf, x, N, t * NT, tid);
    __syncthreads();

    for (int it = 0; it < tpb; it++, t += GRID_OUT) {
        sts_convert(pf, sm, OUT_BH, OUT_BL, tid);
        __syncthreads();
        if (it + 1 < tpb) ldg_tile(pf, x, N, (t + GRID_OUT) * NT, tid);

        float acc[2][2][4];
        mma_tile_acc(uSM, 0, A_IMG, OUT_BH, OUT_BL, lane, wm, wn, acc);
        store_acc(y, N, t * NT, wm, wn, lane, acc, g_b2);
        __syncthreads();
    }
}

// ---------------- compose M and M2 (exact algebraic folds) ----------------
__global__ void compose_M_kernel(const float* __restrict__ w_out) {
    const int tid = threadIdx.x;
    const int o = blockIdx.x * 2 + (tid >> 7);
    const int c2 = tid & 127;
    const int h = c2 >> 5, d = c2 & 31;
    const float invz = 1.0f / g_z[c2];
    const float* wrow = w_out + o * CDIM + h * 32;
    const float* cr = g_ctx + h * (DHEAD * DHEAD) + d * DHEAD;
    float s = 0.0f;
    #pragma unroll
    for (int e = 0; e < 32; e++) s += wrow[e] * cr[e];
    g_M[o * CDIM + c2] = s * invz;
}
__global__ void compose_M2_kernel(const float* __restrict__ w_qkv,
                                  const float* __restrict__ b_qkv,
                                  const float* __restrict__ b_out) {
    const int tid = threadIdx.x;
    const int o = blockIdx.x * 2 + (tid >> 7);
    const int c = tid & 127;
    const float* mrow = g_M + o * CDIM;
    float s = 0.0f;
    #pragma unroll 8
    for (int j = 0; j < CDIM; j++) s += mrow[j] * w_qkv[j * CDIM + c];
    g_M2[o * CDIM + c] = s;
    if (c == 0) {
        float b = b_out[o];
        #pragma unroll 8
        for (int j = 0; j < CDIM; j++) b += mrow[j] * b_qkv[j];
        g_b2[o] = b;
    }
}

// ---------------- launch ----------------
extern "C" void kernel_launch(void* const* d_in, const int* in_sizes, int n_in,
                              void* d_out, int out_size) {
    const float* x     = (const float*)d_in[0];
    const float* w_qkv = (const float*)d_in[1];
    const float* b_qkv = (const float*)d_in[2];
    const float* w_out = (const float*)d_in[3];
    const float* b_out = (const float*)d_in[4];
    float* y = (float*)d_out;

    const int N = in_sizes[0] / CDIM;        // 147456
    const int tpb_kv = (N / NT) / GRID_KV;   // 16
    const int tpb_out = (N / NT) / GRID_OUT; // 8

    cudaFuncSetAttribute(gemm_kv_ctx, cudaFuncAttributeMaxDynamicSharedMemorySize, F_SMEM);
    cudaFuncSetAttribute(gemm_out_tc, cudaFuncAttributeMaxDynamicSharedMemorySize, OUT_SMEM);

    // 1) fused: k,v projection + exp + block-diagonal context partials
    gemm_kv_ctx<<<GRID_KV, 512, F_SMEM>>>(x, w_qkv, b_qkv, N, tpb_kv);

    // 2) reduce partials -> ctx, z
    reduce_ctx_kernel<<<16, 256>>>();

    // 3) exact folds: M = W_out*blockdiag(ctx^T/Z); M2 = M*W_q; b2 = M*b_q + b_out
    compose_M_kernel<<<64, 256>>>(w_out);
    compose_M2_kernel<<<64, 256>>>(w_qkv, b_qkv, b_out);

    // 4) y = M2 @ x + b2
    gemm_out_tc<<<GRID_OUT, 512, OUT_SMEM>>>(x, y, N, tpb_out);
}

// round 15
// speedup vs baseline: 3.7450x; 1.0663x over previous
#include <cuda_runtime.h>
#include <cuda_bf16.h>
#include <cstdint>

// Problem constants (fixed by the dataset)
#define HEADS 4
#define DHEAD 32
#define CDIM  128
#define NTOT  147456          // 384*384
#define NT    64              // n-tile width
#define NTILES (NTOT / NT)    // 2304
#define GRID_KV 144           // kv grid: 1 wave at 1 CTA/SM; tpb = 16
#define GRID_OUT 288          // out grid: 1 wave at 2 CTA/SM; tpb = 8

// ---------------- scratch (static device globals) ----------------
__device__ float g_part[GRID_KV * 4096];       // per-block ctx partials [b][h][d][e]
__device__ float g_zpart[GRID_KV * 128];       // per-block z partials
__device__ float g_ctx[HEADS * DHEAD * DHEAD]; // reduced context [h][d][e]
__device__ float g_z[CDIM];
__device__ float g_M2[CDIM * CDIM];
__device__ float g_b2[CDIM];
__device__ int g_barrier = 0;                  // soft grid barrier (reset by gemm_kv_ctx)

// ---------------- portable primitives ----------------
__device__ __forceinline__ uint32_t smem_u32(const void* p) {
    uint32_t a;
    asm("{ .reg .u64 t; cvta.to.shared.u64 t, %1; cvt.u32.u64 %0, t; }" : "=r"(a) : "l"(p));
    return a;
}
#define LDM_X4(r0, r1, r2, r3, addr) \
    asm volatile("ldmatrix.sync.aligned.m8n8.x4.shared.b16 {%0,%1,%2,%3}, [%4];" \
                 : "=r"(r0), "=r"(r1), "=r"(r2), "=r"(r3) : "r"(addr))
#define LDM_X4_T(r0, r1, r2, r3, addr) \
    asm volatile("ldmatrix.sync.aligned.m8n8.x4.trans.shared.b16 {%0,%1,%2,%3}, [%4];" \
                 : "=r"(r0), "=r"(r1), "=r"(r2), "=r"(r3) : "r"(addr))
#define MMA16816(d, a0, a1, a2, a3, b0, b1) \
    asm volatile("mma.sync.aligned.m16n8k16.row.col.f32.bf16.bf16.f32 " \
                 "{%0,%1,%2,%3}, {%4,%5,%6,%7}, {%8,%9}, {%0,%1,%2,%3};" \
                 : "+f"((d)[0]), "+f"((d)[1]), "+f"((d)[2]), "+f"((d)[3]) \
                 : "r"(a0), "r"(a1), "r"(a2), "r"(a3), "r"(b0), "r"(b1))

__device__ __forceinline__ uint32_t pack_bf2(float a, float b) {
    __nv_bfloat162 t = __floats2bfloat162_rn(a, b);
    return *reinterpret_cast<uint32_t*>(&t);
}
__device__ __forceinline__ void split_pair(float a, float b, uint32_t& hi, uint32_t& lo) {
    __nv_bfloat16 ha = __float2bfloat16(a), hb = __float2bfloat16(b);
    hi = pack_bf2(__bfloat162float(ha), __bfloat162float(hb));
    lo = pack_bf2(a - __bfloat162float(ha), b - __bfloat162float(hb));
}

// smem geometry
#define LDA  136                       // A image row stride (bf16 elems)
#define CLD  72                        // x/ek/v tile row stride (bf16 elems)
#define A_IMG (128 * LDA * 2)          // 34816 B
#define B_IMG (128 * CLD * 2)          // 18432 B
#define F_XBH (4 * A_IMG)
#define F_XBL (4 * A_IMG + B_IMG)
#define F_VH  (4 * A_IMG + 2 * B_IMG)
#define F_VL  (4 * A_IMG + 3 * B_IMG)
#define F_SMEM (4 * A_IMG + 4 * B_IMG)   // 212992
#define OUT_BH (2 * A_IMG)
#define OUT_BL (2 * A_IMG + B_IMG)
#define OUT_SMEM (2 * A_IMG + 2 * B_IMG)  // 106496

// ---------------- HMMA accumulate over staged smem (generic 128x64 tile) ----------------
__device__ __forceinline__ void mma_tile_acc(
    uint32_t uSM, uint32_t offAh, uint32_t offAl, uint32_t offBh, uint32_t offBl,
    int lane, int wm, int wn, float acc[2][2][4])
{
    #pragma unroll
    for (int i = 0; i < 2; i++)
        #pragma unroll
        for (int j = 0; j < 2; j++)
            #pragma unroll
            for (int r = 0; r < 4; r++) acc[i][j][r] = 0.0f;

    const uint32_t a_row = wm * 32 + (lane & 15);
    const uint32_t a_col = (lane >> 4) * 8;
    const uint32_t b_krow = (lane & 7) + ((lane >> 3) & 1) * 8;
    const uint32_t b_noff = ((lane >> 4) & 1) * 8;

    #pragma unroll
    for (int ks = 0; ks < 8; ks++) {
        uint32_t ah[2][4], al[2][4], bh[4], bl[4];
        #pragma unroll
        for (int i = 0; i < 2; i++) {
            uint32_t off = ((a_row + i * 16) * LDA + ks * 16 + a_col) * 2;
            LDM_X4(ah[i][0], ah[i][1], ah[i][2], ah[i][3], uSM + offAh + off);
            LDM_X4(al[i][0], al[i][1], al[i][2], al[i][3], uSM + offAl + off);
        }
        {
            uint32_t boff = ((ks * 16 + b_krow) * CLD + wn * 16 + b_noff) * 2;
            LDM_X4_T(bh[0], bh[1], bh[2], bh[3], uSM + offBh + boff);
            LDM_X4_T(bl[0], bl[1], bl[2], bl[3], uSM + offBl + boff);
        }
        #pragma unroll
        for (int i = 0; i < 2; i++)
            #pragma unroll
            for (int j = 0; j < 2; j++) {
                MMA16816(acc[i][j], ah[i][0], ah[i][1], ah[i][2], ah[i][3], bh[2*j], bh[2*j+1]);
                MMA16816(acc[i][j], ah[i][0], ah[i][1], ah[i][2], ah[i][3], bl[2*j], bl[2*j+1]);
                MMA16816(acc[i][j], al[i][0], al[i][1], al[i][2], al[i][3], bh[2*j], bh[2*j+1]);
            }
    }
}

__device__ __forceinline__ void store_acc(
    float* __restrict__ out, int N, int col0, int wm, int wn, int lane,
    const float acc[2][2][4], const float* __restrict__ bias)
{
    #pragma unroll
    for (int i = 0; i < 2; i++) {
        const int row = wm * 32 + i * 16 + (lane >> 2);
        const float b0 = bias[row], b1 = bias[row + 8];
        #pragma unroll
        for (int j = 0; j < 2; j++) {
            const int col = col0 + wn * 16 + j * 8 + (lane & 3) * 2;
            *reinterpret_cast<float2*>(out + (size_t)row * N + col) =
                make_float2(acc[i][j][0] + b0, acc[i][j][1] + b0);
            *reinterpret_cast<float2*>(out + (size_t)(row + 8) * N + col) =
                make_float2(acc[i][j][2] + b1, acc[i][j][3] + b1);
        }
    }
}

// load x tile [128c][64n] fp32 into 4 float4 regs (512 threads)
__device__ __forceinline__ void ldg_tile(float4 pf[4], const float* __restrict__ x,
                                         int N, int n0, int tid) {
    #pragma unroll
    for (int i = 0; i < 4; i++) {
        int idx = tid + i * 512, r = idx >> 4, q = idx & 15;
        pf[i] = *reinterpret_cast<const float4*>(x + (size_t)r * N + n0 + q * 4);
    }
}
// convert regs -> bf16 hi/lo smem tiles
__device__ __forceinline__ void sts_convert(const float4 pf[4], char* sm,
                                            uint32_t offBh, uint32_t offBl, int tid) {
    #pragma unroll
    for (int i = 0; i < 4; i++) {
        int idx = tid + i * 512, r = idx >> 4, q = idx & 15;
        float4 v = pf[i];
        uint2 hp, lp;
        split_pair(v.x, v.y, hp.x, lp.x);
        split_pair(v.z, v.w, hp.y, lp.y);
        *reinterpret_cast<uint2*>(sm + offBh + (r * CLD + q * 4) * 2) = hp;
        *reinterpret_cast<uint2*>(sm + offBl + (r * CLD + q * 4) * 2) = lp;
    }
}

// ---------------- FUSED: k,v GEMM + exp + block-diagonal context accumulation ----------------
__global__ void __launch_bounds__(512, 1)
gemm_kv_ctx(const float* __restrict__ x, const float* __restrict__ w_qkv,
            const float* __restrict__ b_qkv, int N, int tpb) {
    extern __shared__ __align__(16) char sm[];
    __shared__ float zbuf[128];
    const int tid = threadIdx.x, lane = tid & 31, w = tid >> 5;
    const int wm = w & 3, wn = w >> 2;
    const uint32_t uSM = smem_u32(sm);

    // reset compose_all's soft barrier for this replay (stream-ordered before compose_all)
    if (blockIdx.x == 0 && tid == 0) g_barrier = 0;

    // ctx warp mapping: head = w&3, quadrant = w>>2 -> (d-half, e-half)
    const int chead = w & 3, cq = w >> 2;
    const int dhalf = cq & 1, ehalf = cq >> 1;

    // stage 4 weight images directly from w_qkv (fp32 -> bf16 hi/lo in-block)
    for (int i = tid; i < 8192; i += 512) {
        int r = i >> 5;          // 0..255
        int q = i & 31;          // float4 col
        float4 v = *reinterpret_cast<const float4*>(w_qkv + (size_t)(128 + r) * 128 + q * 4);
        uint2 hp, lp;
        split_pair(v.x, v.y, hp.x, lp.x);
        split_pair(v.z, v.w, hp.y, lp.y);
        int set = r >> 7, rr = r & 127;
        *reinterpret_cast<uint2*>(sm + (set * 2 + 0) * A_IMG + (rr * LDA + q * 4) * 2) = hp;
        *reinterpret_cast<uint2*>(sm + (set * 2 + 1) * A_IMG + (rr * LDA + q * 4) * 2) = lp;
    }
    if (tid < 128) zbuf[tid] = 0.0f;

    float bk[4], bv[4];
    #pragma unroll
    for (int i = 0; i < 2; i++) {
        int r0 = wm * 32 + i * 16 + (lane >> 2);
        bk[2 * i] = b_qkv[128 + r0];      bk[2 * i + 1] = b_qkv[128 + r0 + 8];
        bv[2 * i] = b_qkv[256 + r0];      bv[2 * i + 1] = b_qkv[256 + r0 + 8];
    }

    float accc[2][4];
    #pragma unroll
    for (int j = 0; j < 2; j++)
        #pragma unroll
        for (int r = 0; r < 4; r++) accc[j][r] = 0.0f;
    float zth[4] = {0.f, 0.f, 0.f, 0.f};

    int t = blockIdx.x;
    float4 pf[4];
    ldg_tile(pf, x, N, t * NT, tid);
    __syncthreads();

    const uint32_t a_row = wm * 32 + (lane & 15);
    const uint32_t a_col = (lane >> 4) * 8;
    const uint32_t b_krow = (lane & 7) + ((lane >> 3) & 1) * 8;
    const uint32_t b_noff = ((lane >> 4) & 1) * 8;

    for (int it = 0; it < tpb; it++, t += GRID_KV) {
        sts_convert(pf, sm, F_XBH, F_XBL, tid);
        __syncthreads();
        if (it + 1 < tpb) ldg_tile(pf, x, N, (t + GRID_KV) * NT, tid);

        // fused k+v MMAs sharing one B-fragment load per ks
        float acck[2][2][4], accv[2][2][4];
        #pragma unroll
        for (int i = 0; i < 2; i++)
            #pragma unroll
            for (int j = 0; j < 2; j++)
                #pragma unroll
                for (int r = 0; r < 4; r++) { acck[i][j][r] = 0.0f; accv[i][j][r] = 0.0f; }

        #pragma unroll
        for (int ks = 0; ks < 8; ks++) {
            uint32_t bh[4], bl[4];
            {
                uint32_t boff = ((ks * 16 + b_krow) * CLD + wn * 16 + b_noff) * 2;
                LDM_X4_T(bh[0], bh[1], bh[2], bh[3], uSM + F_XBH + boff);
                LDM_X4_T(bl[0], bl[1], bl[2], bl[3], uSM + F_XBL + boff);
            }
            #pragma unroll
            for (int i = 0; i < 2; i++) {
                uint32_t off = ((a_row + i * 16) * LDA + ks * 16 + a_col) * 2;
                uint32_t ah[4], al[4];
                LDM_X4(ah[0], ah[1], ah[2], ah[3], uSM + 0 * A_IMG + off);  // kh
                LDM_X4(al[0], al[1], al[2], al[3], uSM + 1 * A_IMG + off);  // kl
                #pragma unroll
                for (int j = 0; j < 2; j++) {
                    MMA16816(acck[i][j], ah[0], ah[1], ah[2], ah[3], bh[2*j], bh[2*j+1]);
                    MMA16816(acck[i][j], ah[0], ah[1], ah[2], ah[3], bl[2*j], bl[2*j+1]);
                    MMA16816(acck[i][j], al[0], al[1], al[2], al[3], bh[2*j], bh[2*j+1]);
                }
                LDM_X4(ah[0], ah[1], ah[2], ah[3], uSM + 2 * A_IMG + off);  // vh
                LDM_X4(al[0], al[1], al[2], al[3], uSM + 3 * A_IMG + off);  // vl
                #pragma unroll
                for (int j = 0; j < 2; j++) {
                    MMA16816(accv[i][j], ah[0], ah[1], ah[2], ah[3], bh[2*j], bh[2*j+1]);
                    MMA16816(accv[i][j], ah[0], ah[1], ah[2], ah[3], bl[2*j], bl[2*j+1]);
                    MMA16816(accv[i][j], al[0], al[1], al[2], al[3], bh[2*j], bh[2*j+1]);
                }
            }
        }
        __syncthreads();

        // write ek = exp(k+bias) into XB (hi/lo), v+bias into V; accumulate z
        #pragma unroll
        for (int i = 0; i < 2; i++) {
            const int r0 = wm * 32 + i * 16 + (lane >> 2), r1 = r0 + 8;
            #pragma unroll
            for (int j = 0; j < 2; j++) {
                const int col = wn * 16 + j * 8 + (lane & 3) * 2;
                float e00 = __expf(acck[i][j][0] + bk[2 * i]);
                float e01 = __expf(acck[i][j][1] + bk[2 * i]);
                float e10 = __expf(acck[i][j][2] + bk[2 * i + 1]);
                float e11 = __expf(acck[i][j][3] + bk[2 * i + 1]);
                zth[2 * i]     += e00 + e01;
                zth[2 * i + 1] += e10 + e11;
                uint32_t h0, l0, h1, l1;
                split_pair(e00, e01, h0, l0);
                split_pair(e10, e11, h1, l1);
                *reinterpret_cast<uint32_t*>(sm + F_XBH + (r0 * CLD + col) * 2) = h0;
                *reinterpret_cast<uint32_t*>(sm + F_XBL + (r0 * CLD + col) * 2) = l0;
                *reinterpret_cast<uint32_t*>(sm + F_XBH + (r1 * CLD + col) * 2) = h1;
                *reinterpret_cast<uint32_t*>(sm + F_XBL + (r1 * CLD + col) * 2) = l1;
                float v00 = accv[i][j][0] + bv[2 * i];
                float v01 = accv[i][j][1] + bv[2 * i];
                float v10 = accv[i][j][2] + bv[2 * i + 1];
                float v11 = accv[i][j][3] + bv[2 * i + 1];
                split_pair(v00, v01, h0, l0);
                split_pair(v10, v11, h1, l1);
                *reinterpret_cast<uint32_t*>(sm + F_VH + (r0 * CLD + col) * 2) = h0;
                *reinterpret_cast<uint32_t*>(sm + F_VL + (r0 * CLD + col) * 2) = l0;
                *reinterpret_cast<uint32_t*>(sm + F_VH + (r1 * CLD + col) * 2) = h1;
                *reinterpret_cast<uint32_t*>(sm + F_VL + (r1 * CLD + col) * 2) = l1;
            }
        }
        __syncthreads();

        // block-diagonal ctx MMA
        {
            const uint32_t arow = chead * 32 + dhalf * 16 + (lane & 15);
            const uint32_t erow = chead * 32 + ehalf * 16 + (lane & 15);
            const uint32_t ksub = (lane >> 4) * 8;
            #pragma unroll
            for (int ks = 0; ks < 4; ks++) {
                uint32_t eh[4], el[4], vh4[4], vl4[4];
                uint32_t aoff = (arow * CLD + ks * 16 + ksub) * 2;
                uint32_t boff = (erow * CLD + ks * 16 + ksub) * 2;
                LDM_X4(eh[0], eh[1], eh[2], eh[3], uSM + F_XBH + aoff);
                LDM_X4(el[0], el[1], el[2], el[3], uSM + F_XBL + aoff);
                LDM_X4(vh4[0], vh4[1], vh4[2], vh4[3], uSM + F_VH + boff);
                LDM_X4(vl4[0], vl4[1], vl4[2], vl4[3], uSM + F_VL + boff);
                #pragma unroll
                for (int j = 0; j < 2; j++) {
                    MMA16816(accc[j], eh[0], eh[1], eh[2], eh[3], vh4[j], vh4[j + 2]);
                    MMA16816(accc[j], eh[0], eh[1], eh[2], eh[3], vl4[j], vl4[j + 2]);
                    MMA16816(accc[j], el[0], el[1], el[2], el[3], vh4[j], vh4[j + 2]);
                }
            }
        }
        __syncthreads();
    }

    // ---- write ctx partials ----
    {
        float* part = g_part + (size_t)blockIdx.x * 4096 + chead * 1024;
        const int dloc0 = dhalf * 16 + (lane >> 2);
        #pragma unroll
        for (int j = 0; j < 2; j++) {
            const int eloc = ehalf * 16 + j * 8 + (lane & 3) * 2;
            *reinterpret_cast<float2*>(part + dloc0 * 32 + eloc) =
                make_float2(accc[j][0], accc[j][1]);
            *reinterpret_cast<float2*>(part + (dloc0 + 8) * 32 + eloc) =
                make_float2(accc[j][2], accc[j][3]);
        }
    }
    // ---- z partials ----
    #pragma unroll
    for (int c = 0; c < 4; c++) {
        zth[c] += __shfl_xor_sync(0xffffffffu, zth[c], 1);
        zth[c] += __shfl_xor_sync(0xffffffffu, zth[c], 2);
    }
    if ((lane & 3) == 0) {
        #pragma unroll
        for (int c = 0; c < 4; c++) {
            int row = wm * 32 + (c >> 1) * 16 + (lane >> 2) + (c & 1) * 8;
            atomicAdd(&zbuf[row], zth[c]);
        }
    }
    __syncthreads();
    if (tid < 128) g_zpart[blockIdx.x * 128 + tid] = zbuf[tid];
}

// ---------------- compose_all: reduce + M + M2 + b2 in ONE kernel ----------------
// 128 blocks x 128 threads; block b owns ctx row hd=b, z[b], M row b, M2 row b, b2[b].
// One soft grid barrier after phase 1 (counter reset by gemm_kv_ctx).
__global__ void __launch_bounds__(128)
compose_all(const float* __restrict__ w_out, const float* __restrict__ w_qkv,
            const float* __restrict__ b_qkv, const float* __restrict__ b_out) {
    __shared__ float red[128];
    __shared__ float wrow[128];
    __shared__ float mrow[128];
    const int b = blockIdx.x, tid = threadIdx.x;
    const int e = tid & 31, q = tid >> 5;

    // phase 1a: ctx row b (32 values), 4-way split over 144 partials
    {
        float s = 0.0f;
        #pragma unroll 4
        for (int i = 0; i < 36; i++)
            s += g_part[(size_t)(q * 36 + i) * 4096 + b * 32 + e];
        red[tid] = s;
    }
    __syncthreads();
    if (tid < 32)
        g_ctx[b * 32 + tid] = red[tid] + red[32 + tid] + red[64 + tid] + red[96 + tid];
    __syncthreads();
    // phase 1b: z[b] over 144 partials
    {
        float zs = g_zpart[tid * 128 + b];
        if (tid < GRID_KV - 128) zs += g_zpart[(128 + tid) * 128 + b];
        red[tid] = zs;
    }
    __syncthreads();
    #pragma unroll
    for (int st = 64; st > 0; st >>= 1) {
        if (tid < st) red[tid] += red[tid + st];
        __syncthreads();
    }
    if (tid == 0) g_z[b] = red[0];

    // ---- soft grid barrier ----
    __threadfence();
    if (tid == 0) {
        atomicAdd(&g_barrier, 1);
        while (atomicAdd(&g_barrier, 0) < 128) { }
    }
    __syncthreads();

    // phase 2: M row b (smem only): M[b][c2] = (1/z[c2]) * sum_e w_out[b][h*32+e]*ctx[c2*32+e]
    wrow[tid] = w_out[b * 128 + tid];
    __syncthreads();
    {
        const int c2 = tid, hbase = c2 & 0x60;
        const float* cr = g_ctx + c2 * 32;
        float acc = 0.0f;
        #pragma unroll
        for (int ee = 0; ee < 32; ee++) acc += wrow[hbase + ee] * cr[ee];
        mrow[c2] = acc / g_z[c2];
    }
    __syncthreads();

    // phase 3: M2 row b = mrow . W_q  (needs only this block's M row)
    {
        float acc = 0.0f;
        #pragma unroll 8
        for (int j = 0; j < 128; j++) acc += mrow[j] * w_qkv[j * 128 + tid];
        g_M2[b * 128 + tid] = acc;
    }
    // b2[b] = mrow . b_q + b_out[b]
    red[tid] = mrow[tid] * b_qkv[tid];
    __syncthreads();
    #pragma unroll
    for (int st = 64; st > 0; st >>= 1) {
        if (tid < st) red[tid] += red[tid + st];
        __syncthreads();
    }
    if (tid == 0) g_b2[b] = red[0] + b_out[b];
}

// ---------------- GEMM 2: y = M2 @ x + b2 (M2 converted in-block) ----------------
__global__ void __launch_bounds__(512, 2)
gemm_out_tc(const float* __restrict__ x, float* __restrict__ y, int N, int tpb) {
    extern __shared__ __align__(16) char sm[];
    const int tid = threadIdx.x, lane = tid & 31, w = tid >> 5;
    const int wm = w & 3, wn = w >> 2;
    const uint32_t uSM = smem_u32(sm);

    for (int i = tid; i < 4096; i += 512) {
        int r = i >> 5, q = i & 31;
        float4 v = *reinterpret_cast<const float4*>(g_M2 + r * 128 + q * 4);
        uint2 hp, lp;
        split_pair(v.x, v.y, hp.x, lp.x);
        split_pair(v.z, v.w, hp.y, lp.y);
        *reinterpret_cast<uint2*>(sm + 0 * A_IMG + (r * LDA + q * 4) * 2) = hp;
        *reinterpret_cast<uint2*>(sm + 1 * A_IMG + (r * LDA + q * 4) * 2) = lp;
    }

    int t = blockIdx.x;
    float4 pf[4];
    ldg_tile(pf, x, N, t * NT, tid);
    __syncthreads();

    for (int it = 0; it < tpb; it++, t += GRID_OUT) {
        sts_convert(pf, sm, OUT_BH, OUT_BL, tid);
        __syncthreads();
        if (it + 1 < tpb) ldg_tile(pf, x, N, (t + GRID_OUT) * NT, tid);

        float acc[2][2][4];
        mma_tile_acc(uSM, 0, A_IMG, OUT_BH, OUT_BL, lane, wm, wn, acc);
        store_acc(y, N, t * NT, wm, wn, lane, acc, g_b2);
        __syncthreads();
    }
}

// ---------------- launch ----------------
extern "C" void kernel_launch(void* const* d_in, const int* in_sizes, int n_in,
                              void* d_out, int out_size) {
    const float* x     = (const float*)d_in[0];
    const float* w_qkv = (const float*)d_in[1];
    const float* b_qkv = (const float*)d_in[2];
    const float* w_out = (const float*)d_in[3];
    const float* b_out = (const float*)d_in[4];
    float* y = (float*)d_out;

    const int N = in_sizes[0] / CDIM;        // 147456
    const int tpb_kv = (N / NT) / GRID_KV;   // 16
    const int tpb_out = (N / NT) / GRID_OUT; // 8

    cudaFuncSetAttribute(gemm_kv_ctx, cudaFuncAttributeMaxDynamicSharedMemorySize, F_SMEM);
    cudaFuncSetAttribute(gemm_out_tc, cudaFuncAttributeMaxDynamicSharedMemorySize, OUT_SMEM);

    // 1) fused: k,v projection + exp + block-diagonal context partials (also resets barrier)
    gemm_kv_ctx<<<GRID_KV, 512, F_SMEM>>>(x, w_qkv, b_qkv, N, tpb_kv);

    // 2) single kernel: reduce partials -> ctx,z ; M ; M2 ; b2
    compose_all<<<128, 128>>>(w_out, w_qkv, b_qkv, b_out);

    // 3) y = M2 @ x + b2
    gemm_out_tc<<<GRID_OUT, 512, OUT_SMEM>>>(x, y, N, tpb_out);
}